// round 1
// baseline (speedup 1.0000x reference)
#include <cuda_runtime.h>
#include <math.h>

// Problem constants
#define B 8
#define N 2048
#define D 256
#define BN (B*N)           // 16384 rows

// ---------------- scratch (__device__ globals; no allocations allowed) ----------
__device__ float g_proj[BN * D];     // 16 MB: proj = x@W_fp + b_fp
__device__ float g_rnorm[BN];        // 1/max(||proj_row||,1e-12)
__device__ float g_s[BN];            // sigmoid(proj·w_s + b_s)
__device__ float g_deg[BN];          // row sums of adj (atomic)
__device__ float g_w[BN];            // w[m] = sum_n adj[n,m]/deg[n] (atomic)
__device__ float g_xsum[B * D];      // sum_n x[b,n,d] (atomic)
__device__ float g_rbar[B * D];      // sum_m w[m]*proj[b,m,d] (atomic)

// ---------------- K0: zero the atomic accumulators --------------------------------
__global__ void k_zero() {
    int t = blockIdx.x * blockDim.x + threadIdx.x;
    if (t < BN) { g_deg[t] = 0.f; g_w[t] = 0.f; }
    if (t < B * D) { g_xsum[t] = 0.f; g_rbar[t] = 0.f; }
}

// ---------------- K1: proj = x @ W_fp + b_fp  (M=16384, K=256, N=256) --------------
// 128x128 tile, BK=16, 256 threads, 8x8 microtile.
__global__ void k_proj(const float* __restrict__ x, const float* __restrict__ W,
                       const float* __restrict__ bias) {
    __shared__ float As[16][132];
    __shared__ float Bs[16][132];
    const int row0 = blockIdx.x * 128;
    const int col0 = blockIdx.y * 128;
    const int tid = threadIdx.x;
    const int ty = tid >> 4, tx = tid & 15;

    float acc[8][8] = {};

    for (int k0 = 0; k0 < D; k0 += 16) {
#pragma unroll
        for (int i = 0; i < 8; i++) {
            int idx = tid + i * 256;        // 0..2047
            int r = idx >> 4, kk = idx & 15;
            As[kk][r] = x[(row0 + r) * D + k0 + kk];
        }
#pragma unroll
        for (int i = 0; i < 8; i++) {
            int idx = tid + i * 256;
            int kk = idx >> 7, e = idx & 127;
            Bs[kk][e] = W[(k0 + kk) * D + col0 + e];
        }
        __syncthreads();
#pragma unroll
        for (int kk = 0; kk < 16; kk++) {
            float a[8], bb[8];
#pragma unroll
            for (int j = 0; j < 8; j++) a[j] = As[kk][ty * 8 + j];
#pragma unroll
            for (int j = 0; j < 8; j++) bb[j] = Bs[kk][tx * 8 + j];
#pragma unroll
            for (int iy = 0; iy < 8; iy++)
#pragma unroll
                for (int ix = 0; ix < 8; ix++)
                    acc[iy][ix] += a[iy] * bb[ix];
        }
        __syncthreads();
    }
#pragma unroll
    for (int iy = 0; iy < 8; iy++) {
        int r = row0 + ty * 8 + iy;
#pragma unroll
        for (int ix = 0; ix < 8; ix++) {
            int e = col0 + tx * 8 + ix;
            g_proj[r * D + e] = acc[iy][ix] + bias[e];
        }
    }
}

// ---------------- K2: per-row rnorm and sigmoid scalar -----------------------------
// one warp per row; 8 rows per 256-thread block
__global__ void k_rowstats(const float* __restrict__ ws, const float* __restrict__ bs) {
    int row = blockIdx.x * 8 + (threadIdx.x >> 5);
    int lane = threadIdx.x & 31;
    const float* p = g_proj + row * D;
    float ss = 0.f, dt = 0.f;
#pragma unroll
    for (int j = 0; j < 8; j++) {
        float v = p[lane + j * 32];
        ss += v * v;
        dt += v * ws[lane + j * 32];
    }
#pragma unroll
    for (int o = 16; o > 0; o >>= 1) {
        ss += __shfl_xor_sync(0xffffffffu, ss, o);
        dt += __shfl_xor_sync(0xffffffffu, dt, o);
    }
    if (lane == 0) {
        g_rnorm[row] = 1.0f / fmaxf(sqrtf(ss), 1e-12f);
        g_s[row] = 1.0f / (1.0f + expf(-(dt + bs[0])));
    }
}

// ---------------- K3: adj GEMM (per batch: proj @ proj^T, scaled epilogue) ---------
// C[i][m] = proj_i . proj_m ; adj = max(clip(0.5(s_i+s_m),1e-6,1)*rni*rnm*C, 1e-6)
// 128x128 tile, BK=16, 256 threads, 8x8 microtile. Also accumulates row degrees.
__global__ void k_adj(float* __restrict__ adj_out) {
    __shared__ float As[16][132];
    __shared__ float Bs[16][132];
    __shared__ float rI[128], sI[128], rM[128], sM[128];
    __shared__ float degS[128];

    const int b = blockIdx.z;
    const int i0 = blockIdx.x * 128;
    const int m0 = blockIdx.y * 128;
    const float* PA = g_proj + (b * N + i0) * D;
    const float* PB = g_proj + (b * N + m0) * D;
    const int tid = threadIdx.x;
    const int ty = tid >> 4, tx = tid & 15;

    if (tid < 128) {
        rI[tid] = g_rnorm[b * N + i0 + tid];
        sI[tid] = g_s[b * N + i0 + tid];
        degS[tid] = 0.f;
    } else {
        int t = tid - 128;
        rM[t] = g_rnorm[b * N + m0 + t];
        sM[t] = g_s[b * N + m0 + t];
    }

    float acc[8][8] = {};
    for (int k0 = 0; k0 < D; k0 += 16) {
#pragma unroll
        for (int i = 0; i < 8; i++) {
            int idx = tid + i * 256;
            int r = idx >> 4, kk = idx & 15;
            As[kk][r] = PA[r * D + k0 + kk];
        }
#pragma unroll
        for (int i = 0; i < 8; i++) {
            int idx = tid + i * 256;
            int r = idx >> 4, kk = idx & 15;
            Bs[kk][r] = PB[r * D + k0 + kk];
        }
        __syncthreads();
#pragma unroll
        for (int kk = 0; kk < 16; kk++) {
            float a[8], bb[8];
#pragma unroll
            for (int j = 0; j < 8; j++) a[j] = As[kk][ty * 8 + j];
#pragma unroll
            for (int j = 0; j < 8; j++) bb[j] = Bs[kk][tx * 8 + j];
#pragma unroll
            for (int iy = 0; iy < 8; iy++)
#pragma unroll
                for (int ix = 0; ix < 8; ix++)
                    acc[iy][ix] += a[iy] * bb[ix];
        }
        __syncthreads();
    }

    // epilogue: scale, clamp, write adj (float4), accumulate degrees
    float drow[8] = {};
#pragma unroll
    for (int iy = 0; iy < 8; iy++) {
        int il = ty * 8 + iy;
        float rni = rI[il], si = sI[il];
        int row = b * N + i0 + il;
        float4 v0, v1;
        float tmp[8];
#pragma unroll
        for (int ix = 0; ix < 8; ix++) {
            int ml = tx * 8 + ix;
            float sim = acc[iy][ix] * rni * rM[ml];
            float sc = fminf(fmaxf(0.5f * (si + sM[ml]), 1e-6f), 1.0f);
            float a = fmaxf(sc * sim, 1e-6f);
            tmp[ix] = a;
            drow[iy] += a;
        }
        v0 = make_float4(tmp[0], tmp[1], tmp[2], tmp[3]);
        v1 = make_float4(tmp[4], tmp[5], tmp[6], tmp[7]);
        float4* dst = reinterpret_cast<float4*>(adj_out + row * N + m0 + tx * 8);
        dst[0] = v0;
        dst[1] = v1;
    }
#pragma unroll
    for (int iy = 0; iy < 8; iy++) atomicAdd(&degS[ty * 8 + iy], drow[iy]);
    __syncthreads();
    if (tid < 128) atomicAdd(&g_deg[b * N + i0 + tid], degS[tid]);
}

// ---------------- K4: w[m] = sum_i adj[i][m] / max(deg[i],1e-6) --------------------
// grid (mchunk=8, ichunk=4, b=8); 256 threads; thread = one column m
__global__ void k_wacc(const float* __restrict__ adj) {
    __shared__ float rdeg[512];
    const int b = blockIdx.z, m0 = blockIdx.x * 256, i0 = blockIdx.y * 512;
    const int tid = threadIdx.x;
    for (int j = tid; j < 512; j += 256)
        rdeg[j] = 1.0f / fmaxf(g_deg[b * N + i0 + j], 1e-6f);
    __syncthreads();
    const float* A = adj + (b * N + i0) * N + m0;
    float acc = 0.f;
#pragma unroll 4
    for (int i = 0; i < 512; i++) acc += A[i * N + tid] * rdeg[i];
    atomicAdd(&g_w[b * N + m0 + tid], acc);
}

// ---------------- K5: xsum[b][d] = sum_n x[b][n][d] -------------------------------
__global__ void k_xsum(const float* __restrict__ x) {
    const int b = blockIdx.y, n0 = blockIdx.x * 256, d = threadIdx.x;
    const float* X = x + (b * N + n0) * D;
    float acc = 0.f;
#pragma unroll 4
    for (int n = 0; n < 256; n++) acc += X[n * D + d];
    atomicAdd(&g_xsum[b * D + d], acc);
}

// ---------------- K6: rbar[b][d] = sum_m w[m]*proj[b][m][d] -----------------------
__global__ void k_rbar() {
    __shared__ float wS[256];
    const int b = blockIdx.y, m0 = blockIdx.x * 256, d = threadIdx.x;
    wS[d] = g_w[b * N + m0 + d];
    __syncthreads();
    const float* P = g_proj + (b * N + m0) * D;
    float acc = 0.f;
#pragma unroll 4
    for (int m = 0; m < 256; m++) acc += P[m * D + d] * wS[m];
    atomicAdd(&g_rbar[b * D + d], acc);
}

// ---------------- K7: final projections + LayerNorm -> out[b][d] ------------------
__global__ void k_final(const float* __restrict__ W_rp, const float* __restrict__ b_rp,
                        const float* __restrict__ W_gp, const float* __restrict__ b_gp,
                        const float* __restrict__ gamma, const float* __restrict__ beta,
                        float* __restrict__ out) {
    __shared__ float v[256];
    __shared__ float red[8];
    __shared__ float bcast;
    const int b = blockIdx.x, e = threadIdx.x;
    const int lane = e & 31, warp = e >> 5;

    // rbar (mean over n): divide accumulated sum by N
    v[e] = g_rbar[b * D + e] * (1.0f / (float)N);
    __syncthreads();

    // g1 = rbar @ W_rp + b_rp
    float g1 = b_rp[e];
#pragma unroll 4
    for (int d = 0; d < D; d++) g1 += v[d] * W_rp[d * D + e];
    __syncthreads();
    v[e] = g1;
    __syncthreads();

    // g2 = g1 @ W_gp + b_gp
    float g2 = b_gp[e];
#pragma unroll 4
    for (int d = 0; d < D; d++) g2 += v[d] * W_gp[d * D + e];

    // h = g2 + mean_n(x)
    float h = g2 + g_xsum[b * D + e] * (1.0f / (float)N);

    // LayerNorm over D
    float sum = h;
#pragma unroll
    for (int o = 16; o > 0; o >>= 1) sum += __shfl_xor_sync(0xffffffffu, sum, o);
    if (lane == 0) red[warp] = sum;
    __syncthreads();
    if (e == 0) {
        float s = 0.f;
        for (int i = 0; i < 8; i++) s += red[i];
        bcast = s * (1.0f / (float)D);
    }
    __syncthreads();
    float mu = bcast;
    float c = h - mu;
    float sq = c * c;
#pragma unroll
    for (int o = 16; o > 0; o >>= 1) sq += __shfl_xor_sync(0xffffffffu, sq, o);
    __syncthreads();           // protect red[] reuse
    if (lane == 0) red[warp] = sq;
    __syncthreads();
    if (e == 0) {
        float s = 0.f;
        for (int i = 0; i < 8; i++) s += red[i];
        bcast = s * (1.0f / (float)D);
    }
    __syncthreads();
    float var = bcast;
    out[b * D + e] = c * rsqrtf(var + 1e-5f) * gamma[e] + beta[e];
}

// ---------------- launch ----------------------------------------------------------
extern "C" void kernel_launch(void* const* d_in, const int* in_sizes, int n_in,
                              void* d_out, int out_size) {
    const float* x    = (const float*)d_in[0];
    const float* W_fp = (const float*)d_in[1];
    const float* b_fp = (const float*)d_in[2];
    const float* w_s  = (const float*)d_in[3];
    const float* b_s  = (const float*)d_in[4];
    const float* W_rp = (const float*)d_in[5];
    const float* b_rp = (const float*)d_in[6];
    const float* W_gp = (const float*)d_in[7];
    const float* b_gp = (const float*)d_in[8];
    const float* gamma= (const float*)d_in[9];
    const float* beta = (const float*)d_in[10];

    float* out = (float*)d_out;        // [B,1,D] = 2048 floats
    float* adj = out + B * D;          // [B,N,N] follows

    k_zero<<<64, 256>>>();
    k_proj<<<dim3(BN / 128, D / 128), 256>>>(x, W_fp, b_fp);
    k_rowstats<<<BN / 8, 256>>>(w_s, b_s);
    k_adj<<<dim3(N / 128, N / 128, B), 256>>>(adj);
    k_xsum<<<dim3(N / 256, B), 256>>>(x);
    k_wacc<<<dim3(N / 256, N / 512, B), 256>>>(adj);
    k_rbar<<<dim3(N / 256, B), 256>>>();
    k_final<<<B, 256>>>(W_rp, b_rp, W_gp, b_gp, gamma, beta, out);
}

// round 4
// speedup vs baseline: 1.8070x; 1.8070x over previous
#include <cuda_runtime.h>
#include <cuda_bf16.h>
#include <math.h>
#include <cstdint>

// Problem constants
#define B 8
#define N 2048
#define D 256
#define BN (B*N)           // 16384 rows

// ---------------- scratch (__device__ globals; no allocations allowed) ----------
__device__ float g_proj[BN * D];                  // 16 MB: proj = x@W_fp + b_fp
__device__ __nv_bfloat16 g_q[(size_t)BN * 512];   // 16.8 MB: per row [hi(256) | lo(256)]
__device__ float g_rnorm[BN];        // 1/max(||proj_row||,1e-12)
__device__ float g_s[BN];            // sigmoid(proj·w_s + b_s)
__device__ float g_deg[BN];          // row sums of adj (atomic)
__device__ float g_w[BN];            // w[m] = sum_n adj[n,m]/deg[n] (atomic)
__device__ float g_xsum[B * D];      // sum_n x[b,n,d] (atomic)
__device__ float g_rbar[B * D];      // sum_m w[m]*proj[b,m,d] (atomic)

// ======================= helpers (arch-agnostic PTX only) ==========================
__device__ __forceinline__ uint32_t smem_to_u32(const void* smem_ptr) {
    uint32_t addr;
    asm("{ .reg .u64 tmp; cvta.to.shared.u64 tmp, %1; cvt.u32.u64 %0, tmp; }"
        : "=r"(addr) : "l"(smem_ptr));
    return addr;
}
template<int NG>
__device__ __forceinline__ void cp_async_wait() {
    asm volatile("cp.async.wait_group %0;" :: "n"(NG));
}
__device__ __forceinline__ void cp_async16(uint32_t dst, const void* src) {
    asm volatile("cp.async.cg.shared.global [%0], [%1], 16;" :: "r"(dst), "l"(src));
}
__device__ __forceinline__ void cp_async_commit() {
    asm volatile("cp.async.commit_group;" ::: "memory");
}
__device__ __forceinline__ void ldmatrix_x4(uint32_t& r0, uint32_t& r1,
                                            uint32_t& r2, uint32_t& r3, uint32_t addr) {
    asm volatile("ldmatrix.sync.aligned.m8n8.x4.shared.b16 {%0,%1,%2,%3}, [%4];"
                 : "=r"(r0), "=r"(r1), "=r"(r2), "=r"(r3) : "r"(addr));
}
__device__ __forceinline__ void mma_bf16(float* c, const uint32_t* a, const uint32_t* b) {
    asm volatile(
        "mma.sync.aligned.m16n8k16.row.col.f32.bf16.bf16.f32 "
        "{%0,%1,%2,%3}, {%4,%5,%6,%7}, {%8,%9}, {%0,%1,%2,%3};"
        : "+f"(c[0]), "+f"(c[1]), "+f"(c[2]), "+f"(c[3])
        : "r"(a[0]), "r"(a[1]), "r"(a[2]), "r"(a[3]), "r"(b[0]), "r"(b[1]));
}

// ---------------- K0: zero the atomic accumulators --------------------------------
__global__ void k_zero() {
    int t = blockIdx.x * blockDim.x + threadIdx.x;
    if (t < BN) { g_deg[t] = 0.f; g_w[t] = 0.f; }
    if (t < B * D) { g_xsum[t] = 0.f; g_rbar[t] = 0.f; }
}

// ---------------- K1: proj = x @ W_fp + b_fp; also emit hi/lo bf16 split ----------
__global__ void k_proj(const float* __restrict__ x, const float* __restrict__ W,
                       const float* __restrict__ bias) {
    __shared__ float As[16][132];
    __shared__ float Bs[16][132];
    const int row0 = blockIdx.x * 128;
    const int col0 = blockIdx.y * 128;
    const int tid = threadIdx.x;
    const int ty = tid >> 4, tx = tid & 15;

    float acc[8][8] = {};

    for (int k0 = 0; k0 < D; k0 += 16) {
#pragma unroll
        for (int i = 0; i < 8; i++) {
            int idx = tid + i * 256;
            int r = idx >> 4, kk = idx & 15;
            As[kk][r] = x[(row0 + r) * D + k0 + kk];
        }
#pragma unroll
        for (int i = 0; i < 8; i++) {
            int idx = tid + i * 256;
            int kk = idx >> 7, e = idx & 127;
            Bs[kk][e] = W[(k0 + kk) * D + col0 + e];
        }
        __syncthreads();
#pragma unroll
        for (int kk = 0; kk < 16; kk++) {
            float a[8], bb[8];
#pragma unroll
            for (int j = 0; j < 8; j++) a[j] = As[kk][ty * 8 + j];
#pragma unroll
            for (int j = 0; j < 8; j++) bb[j] = Bs[kk][tx * 8 + j];
#pragma unroll
            for (int iy = 0; iy < 8; iy++)
#pragma unroll
                for (int ix = 0; ix < 8; ix++)
                    acc[iy][ix] += a[iy] * bb[ix];
        }
        __syncthreads();
    }
#pragma unroll
    for (int iy = 0; iy < 8; iy++) {
        int r = row0 + ty * 8 + iy;
#pragma unroll
        for (int ix = 0; ix < 8; ix++) {
            int e = col0 + tx * 8 + ix;
            float v = acc[iy][ix] + bias[e];
            g_proj[r * D + e] = v;
            __nv_bfloat16 h = __float2bfloat16(v);
            __nv_bfloat16 l = __float2bfloat16(v - __bfloat162float(h));
            g_q[(size_t)r * 512 + e] = h;
            g_q[(size_t)r * 512 + 256 + e] = l;
        }
    }
}

// ---------------- K2: per-row rnorm and sigmoid scalar -----------------------------
__global__ void k_rowstats(const float* __restrict__ ws, const float* __restrict__ bs) {
    int row = blockIdx.x * 8 + (threadIdx.x >> 5);
    int lane = threadIdx.x & 31;
    const float* p = g_proj + row * D;
    float ss = 0.f, dt = 0.f;
#pragma unroll
    for (int j = 0; j < 8; j++) {
        float v = p[lane + j * 32];
        ss += v * v;
        dt += v * ws[lane + j * 32];
    }
#pragma unroll
    for (int o = 16; o > 0; o >>= 1) {
        ss += __shfl_xor_sync(0xffffffffu, ss, o);
        dt += __shfl_xor_sync(0xffffffffu, dt, o);
    }
    if (lane == 0) {
        g_rnorm[row] = 1.0f / fmaxf(sqrtf(ss), 1e-12f);
        g_s[row] = 1.0f / (1.0f + expf(-(dt + bs[0])));
    }
}

// ---------------- K3: adj GEMM via warp bf16 mma.sync, 3-term split, symmetric -----
// Upper-triangle tiles only (ti<=tj); off-diagonal tiles mirror their block via an
// smem transpose stage. 3-term split: hi.hi + lo.hi + hi.lo (24 k-chunks of 32).
#define TPAD 80
#define TILE_BYTES (128 * TPAD)
#define NSTEP 24

__global__ void __launch_bounds__(256, 2) k_adj_mma(float* __restrict__ adj_out) {
    __shared__ __align__(16) char smA[2][TILE_BYTES];
    __shared__ __align__(16) char smB[2][TILE_BYTES];
    __shared__ float rI[128], sI[128], rM[128], sM[128];
    __shared__ float sdeg[128], sdegM[128];

    const int tid = threadIdx.x;
    const int lane = tid & 31, w = tid >> 5;
    const int b = blockIdx.z;

    // map blockIdx.x (0..135) -> upper-triangle tile (ti, tj), ti<=tj, 16x16
    int ti = 0, rem = blockIdx.x;
    while (rem >= 16 - ti) { rem -= 16 - ti; ti++; }
    const int tj = ti + rem;
    const int i0 = ti * 128;
    const int m0 = tj * 128;
    const bool offdiag = (ti != tj);

    if (tid < 128) {
        rI[tid] = g_rnorm[b * N + i0 + tid];
        sI[tid] = g_s[b * N + i0 + tid];
        sdeg[tid] = 0.f;
    } else {
        int t = tid - 128;
        rM[t] = g_rnorm[b * N + m0 + t];
        sM[t] = g_s[b * N + m0 + t];
        sdegM[t] = 0.f;
    }

    const __nv_bfloat16* QA = g_q + (size_t)(b * N + i0) * 512;
    const __nv_bfloat16* QB = g_q + (size_t)(b * N + m0) * 512;
    const uint32_t aBase0 = smem_to_u32(smA[0]);
    const uint32_t aBase1 = smem_to_u32(smA[1]);
    const uint32_t bBase0 = smem_to_u32(smB[0]);
    const uint32_t bBase1 = smem_to_u32(smB[1]);

    // per-thread cp.async indices: 512 16B chunks per tile, 2 per thread
    const int r0c = (tid + 0)   >> 2, c0c = (tid + 0)   & 3;
    const int r1c = (tid + 256) >> 2, c1c = (tid + 256) & 3;

    // 3-term schedule: step s -> element offsets within the 512-wide q row
    auto load_chunk = [&](int s, int st) {
        int kb = (s & 7) * 32;
        int ao = (s >= 8 && s < 16) ? 256 + kb : kb;   // lo for middle 8 steps
        int bo = (s >= 16) ? 256 + kb : kb;            // lo for last 8 steps
        uint32_t aB = st ? aBase1 : aBase0;
        uint32_t bB = st ? bBase1 : bBase0;
        cp_async16(aB + r0c * TPAD + c0c * 16, QA + (size_t)r0c * 512 + ao + c0c * 8);
        cp_async16(aB + r1c * TPAD + c1c * 16, QA + (size_t)r1c * 512 + ao + c1c * 8);
        cp_async16(bB + r0c * TPAD + c0c * 16, QB + (size_t)r0c * 512 + bo + c0c * 8);
        cp_async16(bB + r1c * TPAD + c1c * 16, QB + (size_t)r1c * 512 + bo + c1c * 8);
        cp_async_commit();
    };

    const int m_off = (w & 1) * 64;    // 2 warps along m
    const int n_off = (w >> 1) * 32;   // 4 warps along n
    const int lrow = lane & 15;
    const int lseg = (lane >> 4) * 16;

    float acc[4][4][4] = {};

    load_chunk(0, 0);
    for (int ch = 0; ch < NSTEP; ch++) {
        if (ch < NSTEP - 1) {
            load_chunk(ch + 1, (ch + 1) & 1);
            cp_async_wait<1>();
        } else {
            cp_async_wait<0>();
        }
        __syncthreads();

        const int st = ch & 1;
        const uint32_t aB = st ? aBase1 : aBase0;
        const uint32_t bB = st ? bBase1 : bBase0;
#pragma unroll
        for (int kk = 0; kk < 2; kk++) {
            uint32_t afr[4][4];
#pragma unroll
            for (int mt = 0; mt < 4; mt++) {
                uint32_t addr = aB + (m_off + mt * 16 + lrow) * TPAD + kk * 32 + lseg;
                ldmatrix_x4(afr[mt][0], afr[mt][1], afr[mt][2], afr[mt][3], addr);
            }
            uint32_t bfr[4][2];
#pragma unroll
            for (int np = 0; np < 2; np++) {
                uint32_t q0, q1, q2, q3;
                uint32_t addr = bB + (n_off + np * 16 + lrow) * TPAD + kk * 32 + lseg;
                ldmatrix_x4(q0, q1, q2, q3, addr);
                bfr[np * 2][0] = q0; bfr[np * 2][1] = q2;
                bfr[np * 2 + 1][0] = q1; bfr[np * 2 + 1][1] = q3;
            }
#pragma unroll
            for (int mt = 0; mt < 4; mt++)
#pragma unroll
                for (int nt = 0; nt < 4; nt++)
                    mma_bf16(acc[mt][nt], afr[mt], bfr[nt]);
        }
        __syncthreads();
    }

    // ---- epilogue: scale, clamp, write normal block, row sums + column sums ----
    const int gr = lane >> 2, tig = lane & 3;
    float cs0[4] = {}, cs1[4] = {};
#pragma unroll
    for (int mt = 0; mt < 4; mt++) {
        const int r0l = m_off + mt * 16 + gr;
        const int r1l = r0l + 8;
        const float rn0 = rI[r0l], s0 = sI[r0l];
        const float rn1 = rI[r1l], s1 = sI[r1l];
        float* row0p = adj_out + ((size_t)(b * N + i0 + r0l)) * N + m0;
        float* row1p = adj_out + ((size_t)(b * N + i0 + r1l)) * N + m0;
        float d0 = 0.f, d1 = 0.f;
#pragma unroll
        for (int nt = 0; nt < 4; nt++) {
            const int cl = n_off + nt * 8 + tig * 2;
            const float rmA = rM[cl], rmB = rM[cl + 1];
            const float smA_ = sM[cl], smB_ = sM[cl + 1];
            float v00 = fmaxf(fminf(fmaxf(0.5f * (s0 + smA_), 1e-6f), 1.0f) *
                              (acc[mt][nt][0] * rn0 * rmA), 1e-6f);
            float v01 = fmaxf(fminf(fmaxf(0.5f * (s0 + smB_), 1e-6f), 1.0f) *
                              (acc[mt][nt][1] * rn0 * rmB), 1e-6f);
            float v10 = fmaxf(fminf(fmaxf(0.5f * (s1 + smA_), 1e-6f), 1.0f) *
                              (acc[mt][nt][2] * rn1 * rmA), 1e-6f);
            float v11 = fmaxf(fminf(fmaxf(0.5f * (s1 + smB_), 1e-6f), 1.0f) *
                              (acc[mt][nt][3] * rn1 * rmB), 1e-6f);
            d0 += v00 + v01;
            d1 += v10 + v11;
            cs0[nt] += v00 + v10;
            cs1[nt] += v01 + v11;
            *(float2*)(row0p + cl) = make_float2(v00, v01);
            *(float2*)(row1p + cl) = make_float2(v10, v11);
        }
        d0 += __shfl_xor_sync(0xffffffffu, d0, 1);
        d0 += __shfl_xor_sync(0xffffffffu, d0, 2);
        d1 += __shfl_xor_sync(0xffffffffu, d1, 1);
        d1 += __shfl_xor_sync(0xffffffffu, d1, 2);
        if (tig == 0) {
            atomicAdd(&sdeg[r0l], d0);
            atomicAdd(&sdeg[r1l], d1);
        }
    }
    if (offdiag) {
        // column sums -> mirror-row degrees
#pragma unroll
        for (int nt = 0; nt < 4; nt++) {
            float c0 = cs0[nt], c1 = cs1[nt];
#pragma unroll
            for (int o = 4; o < 32; o <<= 1) {
                c0 += __shfl_xor_sync(0xffffffffu, c0, o);
                c1 += __shfl_xor_sync(0xffffffffu, c1, o);
            }
            if (lane < 4) {
                atomicAdd(&sdegM[n_off + nt * 8 + tig * 2], c0);
                atomicAdd(&sdegM[n_off + nt * 8 + tig * 2 + 1], c1);
            }
        }
    }
    __syncthreads();
    if (tid < 128) atomicAdd(&g_deg[b * N + i0 + tid], sdeg[tid]);
    if (offdiag && tid >= 128)
        atomicAdd(&g_deg[b * N + m0 + (tid - 128)], sdegM[tid - 128]);

    // ---- mirror block via smem transpose stage (off-diagonal tiles only) ----
    if (offdiag) {
        float* stage = (float*)smA;        // 32 cols x 132-stride floats = 16.9 KB
        for (int cc = 0; cc < 4; cc++) {
            __syncthreads();
            if ((w >> 1) == cc) {
#pragma unroll
                for (int mt = 0; mt < 4; mt++) {
                    const int r0l = m_off + mt * 16 + gr;
                    const int r1l = r0l + 8;
                    const float rn0 = rI[r0l], s0 = sI[r0l];
                    const float rn1 = rI[r1l], s1 = sI[r1l];
#pragma unroll
                    for (int nt = 0; nt < 4; nt++) {
                        const int cl = n_off + nt * 8 + tig * 2;   // == cc*32 + local
                        const int cL = nt * 8 + tig * 2;
                        const float rmA = rM[cl], rmB = rM[cl + 1];
                        const float smA_ = sM[cl], smB_ = sM[cl + 1];
                        stage[cL * 132 + r0l] =
                            fmaxf(fminf(fmaxf(0.5f * (s0 + smA_), 1e-6f), 1.0f) *
                                  (acc[mt][nt][0] * rn0 * rmA), 1e-6f);
                        stage[(cL + 1) * 132 + r0l] =
                            fmaxf(fminf(fmaxf(0.5f * (s0 + smB_), 1e-6f), 1.0f) *
                                  (acc[mt][nt][1] * rn0 * rmB), 1e-6f);
                        stage[cL * 132 + r1l] =
                            fmaxf(fminf(fmaxf(0.5f * (s1 + smA_), 1e-6f), 1.0f) *
                                  (acc[mt][nt][2] * rn1 * rmA), 1e-6f);
                        stage[(cL + 1) * 132 + r1l] =
                            fmaxf(fminf(fmaxf(0.5f * (s1 + smB_), 1e-6f), 1.0f) *
                                  (acc[mt][nt][3] * rn1 * rmB), 1e-6f);
                    }
                }
            }
            __syncthreads();
            // drain: 256 threads write 32 transposed rows of 128 floats
            const int c = tid >> 3, seg = tid & 7;
            float* dst = adj_out + ((size_t)(b * N + m0 + cc * 32 + c)) * N + i0 + seg * 16;
            const float* srcp = stage + c * 132 + seg * 16;
#pragma unroll
            for (int j = 0; j < 4; j++)
                ((float4*)dst)[j] = make_float4(srcp[4*j], srcp[4*j+1], srcp[4*j+2], srcp[4*j+3]);
        }
    }
}

// ---------------- K4: w[m] = sum_i adj[i][m] / max(deg[i],1e-6) --------------------
__global__ void k_wacc(const float* __restrict__ adj) {
    __shared__ float rdeg[512];
    const int b = blockIdx.z, m0 = blockIdx.x * 256, i0 = blockIdx.y * 512;
    const int tid = threadIdx.x;
    for (int j = tid; j < 512; j += 256)
        rdeg[j] = 1.0f / fmaxf(g_deg[b * N + i0 + j], 1e-6f);
    __syncthreads();
    const float* A = adj + (size_t)(b * N + i0) * N + m0;
    float acc = 0.f;
#pragma unroll 4
    for (int i = 0; i < 512; i++) acc += A[(size_t)i * N + tid] * rdeg[i];
    atomicAdd(&g_w[b * N + m0 + tid], acc);
}

// ---------------- K5: xsum[b][d] = sum_n x[b][n][d] -------------------------------
__global__ void k_xsum(const float* __restrict__ x) {
    const int b = blockIdx.y, n0 = blockIdx.x * 256, d = threadIdx.x;
    const float* X = x + (size_t)(b * N + n0) * D;
    float acc = 0.f;
#pragma unroll 4
    for (int n = 0; n < 256; n++) acc += X[n * D + d];
    atomicAdd(&g_xsum[b * D + d], acc);
}

// ---------------- K6: rbar[b][d] = sum_m w[m]*proj[b][m][d] -----------------------
__global__ void k_rbar() {
    __shared__ float wS[256];
    const int b = blockIdx.y, m0 = blockIdx.x * 256, d = threadIdx.x;
    wS[d] = g_w[b * N + m0 + d];
    __syncthreads();
    const float* P = g_proj + (size_t)(b * N + m0) * D;
    float acc = 0.f;
#pragma unroll 4
    for (int m = 0; m < 256; m++) acc += P[m * D + d] * wS[m];
    atomicAdd(&g_rbar[b * D + d], acc);
}

// ---------------- K7: final projections + LayerNorm -> out[b][d] ------------------
__global__ void k_final(const float* __restrict__ W_rp, const float* __restrict__ b_rp,
                        const float* __restrict__ W_gp, const float* __restrict__ b_gp,
                        const float* __restrict__ gamma, const float* __restrict__ beta,
                        float* __restrict__ out) {
    __shared__ float v[256];
    __shared__ float red[8];
    __shared__ float bcast;
    const int b = blockIdx.x, e = threadIdx.x;
    const int lane = e & 31, warp = e >> 5;

    v[e] = g_rbar[b * D + e] * (1.0f / (float)N);
    __syncthreads();

    float g1 = b_rp[e];
#pragma unroll 4
    for (int d = 0; d < D; d++) g1 += v[d] * W_rp[d * D + e];
    __syncthreads();
    v[e] = g1;
    __syncthreads();

    float g2 = b_gp[e];
#pragma unroll 4
    for (int d = 0; d < D; d++) g2 += v[d] * W_gp[d * D + e];

    float h = g2 + g_xsum[b * D + e] * (1.0f / (float)N);

    float sum = h;
#pragma unroll
    for (int o = 16; o > 0; o >>= 1) sum += __shfl_xor_sync(0xffffffffu, sum, o);
    if (lane == 0) red[warp] = sum;
    __syncthreads();
    if (e == 0) {
        float s = 0.f;
        for (int i = 0; i < 8; i++) s += red[i];
        bcast = s * (1.0f / (float)D);
    }
    __syncthreads();
    float mu = bcast;
    float c = h - mu;
    float sq = c * c;
#pragma unroll
    for (int o = 16; o > 0; o >>= 1) sq += __shfl_xor_sync(0xffffffffu, sq, o);
    __syncthreads();
    if (lane == 0) red[warp] = sq;
    __syncthreads();
    if (e == 0) {
        float s = 0.f;
        for (int i = 0; i < 8; i++) s += red[i];
        bcast = s * (1.0f / (float)D);
    }
    __syncthreads();
    float var = bcast;
    out[b * D + e] = c * rsqrtf(var + 1e-5f) * gamma[e] + beta[e];
}

// ---------------- launch ----------------------------------------------------------
extern "C" void kernel_launch(void* const* d_in, const int* in_sizes, int n_in,
                              void* d_out, int out_size) {
    const float* x    = (const float*)d_in[0];
    const float* W_fp = (const float*)d_in[1];
    const float* b_fp = (const float*)d_in[2];
    const float* w_s  = (const float*)d_in[3];
    const float* b_s  = (const float*)d_in[4];
    const float* W_rp = (const float*)d_in[5];
    const float* b_rp = (const float*)d_in[6];
    const float* W_gp = (const float*)d_in[7];
    const float* b_gp = (const float*)d_in[8];
    const float* gamma= (const float*)d_in[9];
    const float* beta = (const float*)d_in[10];

    float* out = (float*)d_out;        // [B,1,D] = 2048 floats
    float* adj = out + B * D;          // [B,N,N] follows

    k_zero<<<64, 256>>>();
    k_proj<<<dim3(BN / 128, D / 128), 256>>>(x, W_fp, b_fp);
    k_rowstats<<<BN / 8, 256>>>(w_s, b_s);
    k_adj_mma<<<dim3(136, 1, B), 256>>>(adj);
    k_xsum<<<dim3(N / 256, B), 256>>>(x);
    k_wacc<<<dim3(N / 256, N / 512, B), 256>>>(adj);
    k_rbar<<<dim3(N / 256, B), 256>>>();
    k_final<<<B, 256>>>(W_rp, b_rp, W_gp, b_gp, gamma, beta, out);
}

// round 5
// speedup vs baseline: 2.6702x; 1.4777x over previous
#include <cuda_runtime.h>
#include <cuda_bf16.h>
#include <math.h>
#include <cstdint>

// Problem constants
#define B 8
#define N 2048
#define D 256
#define BN (B*N)           // 16384 rows

// ---------------- scratch (__device__ globals; no allocations allowed) ----------
__device__ float g_proj[BN * D];                  // 16 MB: proj = x@W_fp + b_fp
__device__ __nv_bfloat16 g_q[(size_t)BN * 512];   // split of proj: [hi(256) | lo(256)]
__device__ __nv_bfloat16 g_xq[(size_t)BN * 512];  // split of x
__device__ __nv_bfloat16 g_wq[512 * 512];         // split of W_fp^T: row e: [hi(d) | lo(d)]
__device__ float g_rnorm[BN];        // 1/max(||proj_row||,1e-12)
__device__ float g_s[BN];            // sigmoid(proj·w_s + b_s)
__device__ float g_deg[BN];          // row sums of adj (atomic)
__device__ float g_rdeg[BN];         // 1/max(deg,1e-6)
__device__ float g_w[BN];            // w[m] = sum_i adj[m,i]/deg[i]
__device__ float g_xsum[B * D];      // sum_n x[b,n,d] (atomic)
__device__ float g_rbar[B * D];      // sum_m w[m]*proj[b,m,d] (atomic)

// ======================= helpers (arch-agnostic PTX only) ==========================
__device__ __forceinline__ uint32_t smem_to_u32(const void* smem_ptr) {
    uint32_t addr;
    asm("{ .reg .u64 tmp; cvta.to.shared.u64 tmp, %1; cvt.u32.u64 %0, tmp; }"
        : "=r"(addr) : "l"(smem_ptr));
    return addr;
}
template<int NG>
__device__ __forceinline__ void cp_async_wait() {
    asm volatile("cp.async.wait_group %0;" :: "n"(NG));
}
__device__ __forceinline__ void cp_async16(uint32_t dst, const void* src) {
    asm volatile("cp.async.cg.shared.global [%0], [%1], 16;" :: "r"(dst), "l"(src));
}
__device__ __forceinline__ void cp_async_commit() {
    asm volatile("cp.async.commit_group;" ::: "memory");
}
__device__ __forceinline__ void ldmatrix_x4(uint32_t& r0, uint32_t& r1,
                                            uint32_t& r2, uint32_t& r3, uint32_t addr) {
    asm volatile("ldmatrix.sync.aligned.m8n8.x4.shared.b16 {%0,%1,%2,%3}, [%4];"
                 : "=r"(r0), "=r"(r1), "=r"(r2), "=r"(r3) : "r"(addr));
}
__device__ __forceinline__ void mma_bf16(float* c, const uint32_t* a, const uint32_t* b) {
    asm volatile(
        "mma.sync.aligned.m16n8k16.row.col.f32.bf16.bf16.f32 "
        "{%0,%1,%2,%3}, {%4,%5,%6,%7}, {%8,%9}, {%0,%1,%2,%3};"
        : "+f"(c[0]), "+f"(c[1]), "+f"(c[2]), "+f"(c[3])
        : "r"(a[0]), "r"(a[1]), "r"(a[2]), "r"(a[3]), "r"(b[0]), "r"(b[1]));
}

#define TPAD 80
#define TILE_BYTES (128 * TPAD)     // 10240
#define NBUF 4
#define NSTEP 24
#define MMA_BUF_BYTES (NBUF * TILE_BYTES * 2)      // 81920
#define ADJ_SMEM (MMA_BUF_BYTES + 6 * 128 * 4)     // + rI,sI,rM,sM,sdeg,sdegM
#define PROJ_SMEM (MMA_BUF_BYTES + 512)            // + bias[128]

// ---------------- K0: zero the atomic accumulators --------------------------------
__global__ void k_zero() {
    int t = blockIdx.x * blockDim.x + threadIdx.x;
    if (t < BN) g_deg[t] = 0.f;
    if (t < B * D) { g_xsum[t] = 0.f; g_rbar[t] = 0.f; }
}

// ---------------- K-split: hi/lo bf16 split of x and W^T ---------------------------
__global__ void k_split(const float* __restrict__ x, const float* __restrict__ W) {
    int idx = blockIdx.x * 256 + threadIdx.x;
    if (idx < BN * D) {
        int r = idx >> 8, c = idx & 255;
        float v = x[idx];
        __nv_bfloat16 h = __float2bfloat16(v);
        __nv_bfloat16 l = __float2bfloat16(v - __bfloat162float(h));
        g_xq[(size_t)r * 512 + c] = h;
        g_xq[(size_t)r * 512 + 256 + c] = l;
    } else {
        int j = idx - BN * D;          // j < D*D
        int e = j >> 8, d = j & 255;
        float v = W[d * D + e];
        __nv_bfloat16 h = __float2bfloat16(v);
        __nv_bfloat16 l = __float2bfloat16(v - __bfloat162float(h));
        g_wq[e * 512 + d] = h;
        g_wq[e * 512 + 256 + d] = l;
    }
}

// ---------------- K1: proj GEMM on tensor cores (3-term split, K=768) --------------
__global__ void __launch_bounds__(256, 2) k_proj_mma(const float* __restrict__ bias) {
    extern __shared__ __align__(16) char dynsm[];
    char* smA = dynsm;
    char* smB = dynsm + NBUF * TILE_BYTES;
    float* bsh = (float*)(dynsm + MMA_BUF_BYTES);

    const int tid = threadIdx.x;
    const int lane = tid & 31, w = tid >> 5;
    const int i0 = blockIdx.x * 128;
    const int e0 = blockIdx.y * 128;

    if (tid < 128) bsh[tid] = bias[e0 + tid];

    const __nv_bfloat16* QA = g_xq + (size_t)i0 * 512;
    const __nv_bfloat16* QB = g_wq + (size_t)e0 * 512;
    const uint32_t aBase = smem_to_u32(smA);
    const uint32_t bBase = smem_to_u32(smB);

    const int r0c = (tid + 0)   >> 2, c0c = (tid + 0)   & 3;
    const int r1c = (tid + 256) >> 2, c1c = (tid + 256) & 3;

    auto load_chunk = [&](int s, int buf) {
        int kb = (s & 7) * 32;
        int ao = (s >= 8 && s < 16) ? 256 + kb : kb;
        int bo = (s >= 16) ? 256 + kb : kb;
        uint32_t aB = aBase + buf * TILE_BYTES;
        uint32_t bB = bBase + buf * TILE_BYTES;
        cp_async16(aB + r0c * TPAD + c0c * 16, QA + (size_t)r0c * 512 + ao + c0c * 8);
        cp_async16(aB + r1c * TPAD + c1c * 16, QA + (size_t)r1c * 512 + ao + c1c * 8);
        cp_async16(bB + r0c * TPAD + c0c * 16, QB + (size_t)r0c * 512 + bo + c0c * 8);
        cp_async16(bB + r1c * TPAD + c1c * 16, QB + (size_t)r1c * 512 + bo + c1c * 8);
        cp_async_commit();
    };

    const int m_off = (w & 1) * 64;
    const int n_off = (w >> 1) * 32;
    const int lrow = lane & 15;
    const int lseg = (lane >> 4) * 16;

    float acc[4][4][4] = {};

    load_chunk(0, 0); load_chunk(1, 1); load_chunk(2, 2);
    for (int ch = 0; ch < NSTEP; ch++) {
        if (ch <= NSTEP - 3) cp_async_wait<2>();
        else if (ch == NSTEP - 2) cp_async_wait<1>();
        else cp_async_wait<0>();
        __syncthreads();
        if (ch + 3 < NSTEP) load_chunk(ch + 3, (ch + 3) & 3);

        const uint32_t aB = aBase + (ch & 3) * TILE_BYTES;
        const uint32_t bB = bBase + (ch & 3) * TILE_BYTES;
#pragma unroll
        for (int kk = 0; kk < 2; kk++) {
            uint32_t afr[4][4];
#pragma unroll
            for (int mt = 0; mt < 4; mt++) {
                uint32_t addr = aB + (m_off + mt * 16 + lrow) * TPAD + kk * 32 + lseg;
                ldmatrix_x4(afr[mt][0], afr[mt][1], afr[mt][2], afr[mt][3], addr);
            }
            uint32_t bfr[4][2];
#pragma unroll
            for (int np = 0; np < 2; np++) {
                uint32_t q0, q1, q2, q3;
                uint32_t addr = bB + (n_off + np * 16 + lrow) * TPAD + kk * 32 + lseg;
                ldmatrix_x4(q0, q1, q2, q3, addr);
                bfr[np * 2][0] = q0; bfr[np * 2][1] = q2;
                bfr[np * 2 + 1][0] = q1; bfr[np * 2 + 1][1] = q3;
            }
#pragma unroll
            for (int mt = 0; mt < 4; mt++)
#pragma unroll
                for (int nt = 0; nt < 4; nt++)
                    mma_bf16(acc[mt][nt], afr[mt], bfr[nt]);
        }
    }
    __syncthreads();

    // epilogue: bias, write fp32 proj and hi/lo split
    const int gr = lane >> 2, tig = lane & 3;
#pragma unroll
    for (int mt = 0; mt < 4; mt++) {
        const int r0l = m_off + mt * 16 + gr;
        const int r1l = r0l + 8;
        const size_t gr0 = (size_t)(i0 + r0l), gr1 = (size_t)(i0 + r1l);
#pragma unroll
        for (int nt = 0; nt < 4; nt++) {
            const int cl = n_off + nt * 8 + tig * 2;
            float v00 = acc[mt][nt][0] + bsh[cl];
            float v01 = acc[mt][nt][1] + bsh[cl + 1];
            float v10 = acc[mt][nt][2] + bsh[cl];
            float v11 = acc[mt][nt][3] + bsh[cl + 1];
            *(float2*)(g_proj + gr0 * D + e0 + cl) = make_float2(v00, v01);
            *(float2*)(g_proj + gr1 * D + e0 + cl) = make_float2(v10, v11);
            __nv_bfloat16 h00 = __float2bfloat16(v00), h01 = __float2bfloat16(v01);
            __nv_bfloat16 h10 = __float2bfloat16(v10), h11 = __float2bfloat16(v11);
            *(__nv_bfloat162*)(g_q + gr0 * 512 + e0 + cl) = __halves2bfloat162(h00, h01);
            *(__nv_bfloat162*)(g_q + gr1 * 512 + e0 + cl) = __halves2bfloat162(h10, h11);
            __nv_bfloat16 l00 = __float2bfloat16(v00 - __bfloat162float(h00));
            __nv_bfloat16 l01 = __float2bfloat16(v01 - __bfloat162float(h01));
            __nv_bfloat16 l10 = __float2bfloat16(v10 - __bfloat162float(h10));
            __nv_bfloat16 l11 = __float2bfloat16(v11 - __bfloat162float(h11));
            *(__nv_bfloat162*)(g_q + gr0 * 512 + 256 + e0 + cl) = __halves2bfloat162(l00, l01);
            *(__nv_bfloat162*)(g_q + gr1 * 512 + 256 + e0 + cl) = __halves2bfloat162(l10, l11);
        }
    }
}

// ---------------- K2: per-row rnorm and sigmoid scalar -----------------------------
__global__ void k_rowstats(const float* __restrict__ ws, const float* __restrict__ bs) {
    int row = blockIdx.x * 8 + (threadIdx.x >> 5);
    int lane = threadIdx.x & 31;
    const float* p = g_proj + (size_t)row * D;
    float ss = 0.f, dt = 0.f;
#pragma unroll
    for (int j = 0; j < 8; j++) {
        float v = p[lane + j * 32];
        ss += v * v;
        dt += v * ws[lane + j * 32];
    }
#pragma unroll
    for (int o = 16; o > 0; o >>= 1) {
        ss += __shfl_xor_sync(0xffffffffu, ss, o);
        dt += __shfl_xor_sync(0xffffffffu, dt, o);
    }
    if (lane == 0) {
        g_rnorm[row] = 1.0f / fmaxf(sqrtf(ss), 1e-12f);
        g_s[row] = 1.0f / (1.0f + expf(-(dt + bs[0])));
    }
}

// ---------------- K3: adj GEMM via warp bf16 mma.sync, 3-term split, symmetric -----
__global__ void __launch_bounds__(256, 2) k_adj_mma(float* __restrict__ adj_out) {
    extern __shared__ __align__(16) char dynsm[];
    char* smA = dynsm;
    char* smB = dynsm + NBUF * TILE_BYTES;
    float* aux = (float*)(dynsm + MMA_BUF_BYTES);
    float* rI = aux;          float* sI = aux + 128;
    float* rM = aux + 256;    float* sM = aux + 384;
    float* sdeg = aux + 512;  float* sdegM = aux + 640;

    const int tid = threadIdx.x;
    const int lane = tid & 31, w = tid >> 5;
    const int b = blockIdx.z;

    // map blockIdx.x (0..135) -> upper-triangle tile (ti, tj), ti<=tj, 16x16
    int ti = 0, rem = blockIdx.x;
    while (rem >= 16 - ti) { rem -= 16 - ti; ti++; }
    const int tj = ti + rem;
    const int i0 = ti * 128;
    const int m0 = tj * 128;
    const bool offdiag = (ti != tj);

    if (tid < 128) {
        rI[tid] = g_rnorm[b * N + i0 + tid];
        sI[tid] = g_s[b * N + i0 + tid];
        sdeg[tid] = 0.f;
    } else {
        int t = tid - 128;
        rM[t] = g_rnorm[b * N + m0 + t];
        sM[t] = g_s[b * N + m0 + t];
        sdegM[t] = 0.f;
    }

    const __nv_bfloat16* QA = g_q + (size_t)(b * N + i0) * 512;
    const __nv_bfloat16* QB = g_q + (size_t)(b * N + m0) * 512;
    const uint32_t aBase = smem_to_u32(smA);
    const uint32_t bBase = smem_to_u32(smB);

    const int r0c = (tid + 0)   >> 2, c0c = (tid + 0)   & 3;
    const int r1c = (tid + 256) >> 2, c1c = (tid + 256) & 3;

    auto load_chunk = [&](int s, int buf) {
        int kb = (s & 7) * 32;
        int ao = (s >= 8 && s < 16) ? 256 + kb : kb;
        int bo = (s >= 16) ? 256 + kb : kb;
        uint32_t aB = aBase + buf * TILE_BYTES;
        uint32_t bB = bBase + buf * TILE_BYTES;
        cp_async16(aB + r0c * TPAD + c0c * 16, QA + (size_t)r0c * 512 + ao + c0c * 8);
        cp_async16(aB + r1c * TPAD + c1c * 16, QA + (size_t)r1c * 512 + ao + c1c * 8);
        cp_async16(bB + r0c * TPAD + c0c * 16, QB + (size_t)r0c * 512 + bo + c0c * 8);
        cp_async16(bB + r1c * TPAD + c1c * 16, QB + (size_t)r1c * 512 + bo + c1c * 8);
        cp_async_commit();
    };

    const int m_off = (w & 1) * 64;
    const int n_off = (w >> 1) * 32;
    const int lrow = lane & 15;
    const int lseg = (lane >> 4) * 16;

    float acc[4][4][4] = {};

    load_chunk(0, 0); load_chunk(1, 1); load_chunk(2, 2);
    for (int ch = 0; ch < NSTEP; ch++) {
        if (ch <= NSTEP - 3) cp_async_wait<2>();
        else if (ch == NSTEP - 2) cp_async_wait<1>();
        else cp_async_wait<0>();
        __syncthreads();
        if (ch + 3 < NSTEP) load_chunk(ch + 3, (ch + 3) & 3);

        const uint32_t aB = aBase + (ch & 3) * TILE_BYTES;
        const uint32_t bB = bBase + (ch & 3) * TILE_BYTES;
#pragma unroll
        for (int kk = 0; kk < 2; kk++) {
            uint32_t afr[4][4];
#pragma unroll
            for (int mt = 0; mt < 4; mt++) {
                uint32_t addr = aB + (m_off + mt * 16 + lrow) * TPAD + kk * 32 + lseg;
                ldmatrix_x4(afr[mt][0], afr[mt][1], afr[mt][2], afr[mt][3], addr);
            }
            uint32_t bfr[4][2];
#pragma unroll
            for (int np = 0; np < 2; np++) {
                uint32_t q0, q1, q2, q3;
                uint32_t addr = bB + (n_off + np * 16 + lrow) * TPAD + kk * 32 + lseg;
                ldmatrix_x4(q0, q1, q2, q3, addr);
                bfr[np * 2][0] = q0; bfr[np * 2][1] = q2;
                bfr[np * 2 + 1][0] = q1; bfr[np * 2 + 1][1] = q3;
            }
#pragma unroll
            for (int mt = 0; mt < 4; mt++)
#pragma unroll
                for (int nt = 0; nt < 4; nt++)
                    mma_bf16(acc[mt][nt], afr[mt], bfr[nt]);
        }
    }
    __syncthreads();

    // ---- epilogue: scale, clamp, write normal block, row sums + column sums ----
    const int gr = lane >> 2, tig = lane & 3;
    float cs0[4] = {}, cs1[4] = {};
#pragma unroll
    for (int mt = 0; mt < 4; mt++) {
        const int r0l = m_off + mt * 16 + gr;
        const int r1l = r0l + 8;
        const float rn0 = rI[r0l], s0 = sI[r0l];
        const float rn1 = rI[r1l], s1 = sI[r1l];
        float* row0p = adj_out + ((size_t)(b * N + i0 + r0l)) * N + m0;
        float* row1p = adj_out + ((size_t)(b * N + i0 + r1l)) * N + m0;
        float d0 = 0.f, d1 = 0.f;
#pragma unroll
        for (int nt = 0; nt < 4; nt++) {
            const int cl = n_off + nt * 8 + tig * 2;
            const float rmA = rM[cl], rmB = rM[cl + 1];
            const float smA_ = sM[cl], smB_ = sM[cl + 1];
            float v00 = fmaxf(fminf(fmaxf(0.5f * (s0 + smA_), 1e-6f), 1.0f) *
                              (acc[mt][nt][0] * rn0 * rmA), 1e-6f);
            float v01 = fmaxf(fminf(fmaxf(0.5f * (s0 + smB_), 1e-6f), 1.0f) *
                              (acc[mt][nt][1] * rn0 * rmB), 1e-6f);
            float v10 = fmaxf(fminf(fmaxf(0.5f * (s1 + smA_), 1e-6f), 1.0f) *
                              (acc[mt][nt][2] * rn1 * rmA), 1e-6f);
            float v11 = fmaxf(fminf(fmaxf(0.5f * (s1 + smB_), 1e-6f), 1.0f) *
                              (acc[mt][nt][3] * rn1 * rmB), 1e-6f);
            d0 += v00 + v01;
            d1 += v10 + v11;
            cs0[nt] += v00 + v10;
            cs1[nt] += v01 + v11;
            *(float2*)(row0p + cl) = make_float2(v00, v01);
            *(float2*)(row1p + cl) = make_float2(v10, v11);
        }
        d0 += __shfl_xor_sync(0xffffffffu, d0, 1);
        d0 += __shfl_xor_sync(0xffffffffu, d0, 2);
        d1 += __shfl_xor_sync(0xffffffffu, d1, 1);
        d1 += __shfl_xor_sync(0xffffffffu, d1, 2);
        if (tig == 0) {
            atomicAdd(&sdeg[r0l], d0);
            atomicAdd(&sdeg[r1l], d1);
        }
    }
    if (offdiag) {
#pragma unroll
        for (int nt = 0; nt < 4; nt++) {
            float c0 = cs0[nt], c1 = cs1[nt];
#pragma unroll
            for (int o = 4; o < 32; o <<= 1) {
                c0 += __shfl_xor_sync(0xffffffffu, c0, o);
                c1 += __shfl_xor_sync(0xffffffffu, c1, o);
            }
            if (lane < 4) {
                atomicAdd(&sdegM[n_off + nt * 8 + tig * 2], c0);
                atomicAdd(&sdegM[n_off + nt * 8 + tig * 2 + 1], c1);
            }
        }
    }
    __syncthreads();
    if (tid < 128) atomicAdd(&g_deg[b * N + i0 + tid], sdeg[tid]);
    if (offdiag && tid >= 128)
        atomicAdd(&g_deg[b * N + m0 + (tid - 128)], sdegM[tid - 128]);

    // ---- mirror block via smem transpose stage (off-diagonal tiles only) ----
    if (offdiag) {
        float* stage = (float*)dynsm;      // reuse A buffers (16.9 KB needed)
        for (int cc = 0; cc < 4; cc++) {
            __syncthreads();
            if ((w >> 1) == cc) {
#pragma unroll
                for (int mt = 0; mt < 4; mt++) {
                    const int r0l = m_off + mt * 16 + gr;
                    const int r1l = r0l + 8;
                    const float rn0 = rI[r0l], s0 = sI[r0l];
                    const float rn1 = rI[r1l], s1 = sI[r1l];
#pragma unroll
                    for (int nt = 0; nt < 4; nt++) {
                        const int cl = n_off + nt * 8 + tig * 2;
                        const int cL = nt * 8 + tig * 2;
                        const float rmA = rM[cl], rmB = rM[cl + 1];
                        const float smA_ = sM[cl], smB_ = sM[cl + 1];
                        stage[cL * 132 + r0l] =
                            fmaxf(fminf(fmaxf(0.5f * (s0 + smA_), 1e-6f), 1.0f) *
                                  (acc[mt][nt][0] * rn0 * rmA), 1e-6f);
                        stage[(cL + 1) * 132 + r0l] =
                            fmaxf(fminf(fmaxf(0.5f * (s0 + smB_), 1e-6f), 1.0f) *
                                  (acc[mt][nt][1] * rn0 * rmB), 1e-6f);
                        stage[cL * 132 + r1l] =
                            fmaxf(fminf(fmaxf(0.5f * (s1 + smA_), 1e-6f), 1.0f) *
                                  (acc[mt][nt][2] * rn1 * rmA), 1e-6f);
                        stage[(cL + 1) * 132 + r1l] =
                            fmaxf(fminf(fmaxf(0.5f * (s1 + smB_), 1e-6f), 1.0f) *
                                  (acc[mt][nt][3] * rn1 * rmB), 1e-6f);
                    }
                }
            }
            __syncthreads();
            const int c = tid >> 3, seg = tid & 7;
            float* dst = adj_out + ((size_t)(b * N + m0 + cc * 32 + c)) * N + i0 + seg * 16;
            const float* srcp = stage + c * 132 + seg * 16;
#pragma unroll
            for (int j = 0; j < 4; j++)
                ((float4*)dst)[j] = make_float4(srcp[4*j], srcp[4*j+1], srcp[4*j+2], srcp[4*j+3]);
        }
    }
}

// ---------------- K-rdeg: reciprocal degrees --------------------------------------
__global__ void k_rdeg() {
    int t = blockIdx.x * blockDim.x + threadIdx.x;
    if (t < BN) g_rdeg[t] = 1.0f / fmaxf(g_deg[t], 1e-6f);
}

// ---------------- K4: w[m] = sum_i adj[m,i] * rdeg[i]  (adj symmetric) -------------
// warp per row m, coalesced row reads; no atomics.
__global__ void k_wacc_row(const float* __restrict__ adj) {
    const int b = blockIdx.y;
    const int m = blockIdx.x * 8 + (threadIdx.x >> 5);
    const int lane = threadIdx.x & 31;
    const float* A = adj + ((size_t)(b * N + m)) * N;
    const float* rd = g_rdeg + b * N;
    float acc = 0.f;
#pragma unroll 8
    for (int j = 0; j < 64; j++) {
        int i = lane + j * 32;
        acc += A[i] * rd[i];
    }
#pragma unroll
    for (int o = 16; o > 0; o >>= 1) acc += __shfl_xor_sync(0xffffffffu, acc, o);
    if (lane == 0) g_w[b * N + m] = acc;
}

// ---------------- K5: xsum[b][d] = sum_n x[b][n][d] -------------------------------
__global__ void k_xsum(const float* __restrict__ x) {
    const int b = blockIdx.y, n0 = blockIdx.x * 64, d = threadIdx.x;
    const float* X = x + (size_t)(b * N + n0) * D;
    float acc = 0.f;
#pragma unroll 8
    for (int n = 0; n < 64; n++) acc += X[n * D + d];
    atomicAdd(&g_xsum[b * D + d], acc);
}

// ---------------- K6: rbar[b][d] = sum_m w[m]*proj[b][m][d] -----------------------
__global__ void k_rbar() {
    __shared__ float wS[64];
    const int b = blockIdx.y, m0 = blockIdx.x * 64, d = threadIdx.x;
    if (d < 64) wS[d] = g_w[b * N + m0 + d];
    __syncthreads();
    const float* P = g_proj + (size_t)(b * N + m0) * D;
    float acc = 0.f;
#pragma unroll 8
    for (int m = 0; m < 64; m++) acc += P[m * D + d] * wS[m];
    atomicAdd(&g_rbar[b * D + d], acc);
}

// ---------------- K7: final projections + LayerNorm -> out[b][d] ------------------
__global__ void k_final(const float* __restrict__ W_rp, const float* __restrict__ b_rp,
                        const float* __restrict__ W_gp, const float* __restrict__ b_gp,
                        const float* __restrict__ gamma, const float* __restrict__ beta,
                        float* __restrict__ out) {
    __shared__ float v[256];
    __shared__ float red[8];
    __shared__ float bcast;
    const int b = blockIdx.x, e = threadIdx.x;
    const int lane = e & 31, warp = e >> 5;

    v[e] = g_rbar[b * D + e] * (1.0f / (float)N);
    __syncthreads();

    float g1 = b_rp[e];
#pragma unroll 4
    for (int d = 0; d < D; d++) g1 += v[d] * W_rp[d * D + e];
    __syncthreads();
    v[e] = g1;
    __syncthreads();

    float g2 = b_gp[e];
#pragma unroll 4
    for (int d = 0; d < D; d++) g2 += v[d] * W_gp[d * D + e];

    float h = g2 + g_xsum[b * D + e] * (1.0f / (float)N);

    float sum = h;
#pragma unroll
    for (int o = 16; o > 0; o >>= 1) sum += __shfl_xor_sync(0xffffffffu, sum, o);
    if (lane == 0) red[warp] = sum;
    __syncthreads();
    if (e == 0) {
        float s = 0.f;
        for (int i = 0; i < 8; i++) s += red[i];
        bcast = s * (1.0f / (float)D);
    }
    __syncthreads();
    float mu = bcast;
    float c = h - mu;
    float sq = c * c;
#pragma unroll
    for (int o = 16; o > 0; o >>= 1) sq += __shfl_xor_sync(0xffffffffu, sq, o);
    __syncthreads();
    if (lane == 0) red[warp] = sq;
    __syncthreads();
    if (e == 0) {
        float s = 0.f;
        for (int i = 0; i < 8; i++) s += red[i];
        bcast = s * (1.0f / (float)D);
    }
    __syncthreads();
    float var = bcast;
    out[b * D + e] = c * rsqrtf(var + 1e-5f) * gamma[e] + beta[e];
}

// ---------------- launch ----------------------------------------------------------
extern "C" void kernel_launch(void* const* d_in, const int* in_sizes, int n_in,
                              void* d_out, int out_size) {
    const float* x    = (const float*)d_in[0];
    const float* W_fp = (const float*)d_in[1];
    const float* b_fp = (const float*)d_in[2];
    const float* w_s  = (const float*)d_in[3];
    const float* b_s  = (const float*)d_in[4];
    const float* W_rp = (const float*)d_in[5];
    const float* b_rp = (const float*)d_in[6];
    const float* W_gp = (const float*)d_in[7];
    const float* b_gp = (const float*)d_in[8];
    const float* gamma= (const float*)d_in[9];
    const float* beta = (const float*)d_in[10];

    float* out = (float*)d_out;        // [B,1,D] = 2048 floats
    float* adj = out + B * D;          // [B,N,N] follows

    cudaFuncSetAttribute(k_adj_mma, cudaFuncAttributeMaxDynamicSharedMemorySize, ADJ_SMEM);
    cudaFuncSetAttribute(k_proj_mma, cudaFuncAttributeMaxDynamicSharedMemorySize, PROJ_SMEM);

    k_zero<<<64, 256>>>();
    k_split<<<(BN * D + D * D) / 256, 256>>>(x, W_fp);
    k_proj_mma<<<dim3(BN / 128, 2), 256, PROJ_SMEM>>>(b_fp);
    k_rowstats<<<BN / 8, 256>>>(w_s, b_s);
    k_adj_mma<<<dim3(136, 1, B), 256, ADJ_SMEM>>>(adj);
    k_rdeg<<<64, 256>>>();
    k_xsum<<<dim3(N / 64, B), 256>>>(x);
    k_wacc_row<<<dim3(N / 8, B), 256>>>(adj);
    k_rbar<<<dim3(N / 64, B), 256>>>();
    k_final<<<B, 256>>>(W_rp, b_rp, W_gp, b_gp, gamma, beta, out);
}

// round 6
// speedup vs baseline: 3.3904x; 1.2697x over previous
#include <cuda_runtime.h>
#include <cuda_bf16.h>
#include <cuda_fp16.h>
#include <math.h>
#include <cstdint>

// Problem constants
#define B 8
#define N 2048
#define D 256
#define BN (B*N)           // 16384 rows

// ---------------- scratch (__device__ globals; no allocations allowed) ----------
__device__ float g_proj[BN * D];                  // 16 MB: proj = x@W_fp + b_fp
__device__ __half g_qh[(size_t)BN * 256];         // 8.4 MB: fp16 of proj (adj GEMM input)
__device__ __nv_bfloat16 g_xq[(size_t)BN * 512];  // split of x: [hi(256) | lo(256)]
__device__ __nv_bfloat16 g_wq[512 * 512];         // split of W_fp^T: row e: [hi(d) | lo(d)]
__device__ float g_rnorm[BN];        // 1/max(||proj_row||,1e-12)
__device__ float g_s[BN];            // sigmoid(proj·w_s + b_s)
__device__ float g_deg[BN];          // row sums of adj (atomic)
__device__ float g_rdeg[BN];         // 1/max(deg,1e-6)
__device__ float g_w[BN];            // w[m] = sum_i adj[m,i]/deg[i]
__device__ float g_xsum[B * D];      // sum_n x[b,n,d] (atomic)
__device__ float g_rbar[B * D];      // sum_m w[m]*proj[b,m,d] (atomic)

// ======================= helpers (arch-agnostic PTX only) ==========================
__device__ __forceinline__ uint32_t smem_to_u32(const void* smem_ptr) {
    uint32_t addr;
    asm("{ .reg .u64 tmp; cvta.to.shared.u64 tmp, %1; cvt.u32.u64 %0, tmp; }"
        : "=r"(addr) : "l"(smem_ptr));
    return addr;
}
template<int NG>
__device__ __forceinline__ void cp_async_wait() {
    asm volatile("cp.async.wait_group %0;" :: "n"(NG));
}
__device__ __forceinline__ void cp_async16(uint32_t dst, const void* src) {
    asm volatile("cp.async.cg.shared.global [%0], [%1], 16;" :: "r"(dst), "l"(src));
}
__device__ __forceinline__ void cp_async_commit() {
    asm volatile("cp.async.commit_group;" ::: "memory");
}
__device__ __forceinline__ void ldmatrix_x4(uint32_t& r0, uint32_t& r1,
                                            uint32_t& r2, uint32_t& r3, uint32_t addr) {
    asm volatile("ldmatrix.sync.aligned.m8n8.x4.shared.b16 {%0,%1,%2,%3}, [%4];"
                 : "=r"(r0), "=r"(r1), "=r"(r2), "=r"(r3) : "r"(addr));
}
__device__ __forceinline__ void mma_bf16(float* c, const uint32_t* a, const uint32_t* b) {
    asm volatile(
        "mma.sync.aligned.m16n8k16.row.col.f32.bf16.bf16.f32 "
        "{%0,%1,%2,%3}, {%4,%5,%6,%7}, {%8,%9}, {%0,%1,%2,%3};"
        : "+f"(c[0]), "+f"(c[1]), "+f"(c[2]), "+f"(c[3])
        : "r"(a[0]), "r"(a[1]), "r"(a[2]), "r"(a[3]), "r"(b[0]), "r"(b[1]));
}
__device__ __forceinline__ void mma_f16(float* c, const uint32_t* a, const uint32_t* b) {
    asm volatile(
        "mma.sync.aligned.m16n8k16.row.col.f32.f16.f16.f32 "
        "{%0,%1,%2,%3}, {%4,%5,%6,%7}, {%8,%9}, {%0,%1,%2,%3};"
        : "+f"(c[0]), "+f"(c[1]), "+f"(c[2]), "+f"(c[3])
        : "r"(a[0]), "r"(a[1]), "r"(a[2]), "r"(a[3]), "r"(b[0]), "r"(b[1]));
}

#define TPAD 80
#define TILE_BYTES (128 * TPAD)     // 10240
#define NBUF 4
#define NSTEP_PROJ 24
#define NSTEP_ADJ 8
#define MMA_BUF_BYTES (NBUF * TILE_BYTES * 2)      // 81920
#define ADJ_SMEM (MMA_BUF_BYTES + 6 * 128 * 4)     // + rI,sI,rM,sM,sdeg,sdegM
#define PROJ_SMEM (MMA_BUF_BYTES + 512)            // + bias[128]

// ---------------- K0: zero the atomic accumulators --------------------------------
__global__ void k_zero() {
    int t = blockIdx.x * blockDim.x + threadIdx.x;
    if (t < BN) g_deg[t] = 0.f;
    if (t < B * D) { g_xsum[t] = 0.f; g_rbar[t] = 0.f; }
}

// ---------------- K-split: hi/lo bf16 split of x and W^T ---------------------------
__global__ void k_split(const float* __restrict__ x, const float* __restrict__ W) {
    int idx = blockIdx.x * 256 + threadIdx.x;
    if (idx < BN * D) {
        int r = idx >> 8, c = idx & 255;
        float v = x[idx];
        __nv_bfloat16 h = __float2bfloat16(v);
        __nv_bfloat16 l = __float2bfloat16(v - __bfloat162float(h));
        g_xq[(size_t)r * 512 + c] = h;
        g_xq[(size_t)r * 512 + 256 + c] = l;
    } else {
        int j = idx - BN * D;          // j < D*D
        int e = j >> 8, d = j & 255;
        float v = W[d * D + e];
        __nv_bfloat16 h = __float2bfloat16(v);
        __nv_bfloat16 l = __float2bfloat16(v - __bfloat162float(h));
        g_wq[e * 512 + d] = h;
        g_wq[e * 512 + 256 + d] = l;
    }
}

// ---------------- K1: proj GEMM on tensor cores (3-term bf16 split, K=768) ---------
__global__ void __launch_bounds__(256, 2) k_proj_mma(const float* __restrict__ bias) {
    extern __shared__ __align__(16) char dynsm[];
    char* smA = dynsm;
    char* smB = dynsm + NBUF * TILE_BYTES;
    float* bsh = (float*)(dynsm + MMA_BUF_BYTES);

    const int tid = threadIdx.x;
    const int lane = tid & 31, w = tid >> 5;
    const int i0 = blockIdx.x * 128;
    const int e0 = blockIdx.y * 128;

    if (tid < 128) bsh[tid] = bias[e0 + tid];

    const __nv_bfloat16* QA = g_xq + (size_t)i0 * 512;
    const __nv_bfloat16* QB = g_wq + (size_t)e0 * 512;
    const uint32_t aBase = smem_to_u32(smA);
    const uint32_t bBase = smem_to_u32(smB);

    const int r0c = (tid + 0)   >> 2, c0c = (tid + 0)   & 3;
    const int r1c = (tid + 256) >> 2, c1c = (tid + 256) & 3;

    auto load_chunk = [&](int s, int buf) {
        int kb = (s & 7) * 32;
        int ao = (s >= 8 && s < 16) ? 256 + kb : kb;
        int bo = (s >= 16) ? 256 + kb : kb;
        uint32_t aB = aBase + buf * TILE_BYTES;
        uint32_t bB = bBase + buf * TILE_BYTES;
        cp_async16(aB + r0c * TPAD + c0c * 16, QA + (size_t)r0c * 512 + ao + c0c * 8);
        cp_async16(aB + r1c * TPAD + c1c * 16, QA + (size_t)r1c * 512 + ao + c1c * 8);
        cp_async16(bB + r0c * TPAD + c0c * 16, QB + (size_t)r0c * 512 + bo + c0c * 8);
        cp_async16(bB + r1c * TPAD + c1c * 16, QB + (size_t)r1c * 512 + bo + c1c * 8);
        cp_async_commit();
    };

    const int m_off = (w & 1) * 64;
    const int n_off = (w >> 1) * 32;
    const int lrow = lane & 15;
    const int lseg = (lane >> 4) * 16;

    float acc[4][4][4] = {};

    load_chunk(0, 0); load_chunk(1, 1); load_chunk(2, 2);
    for (int ch = 0; ch < NSTEP_PROJ; ch++) {
        if (ch <= NSTEP_PROJ - 3) cp_async_wait<2>();
        else if (ch == NSTEP_PROJ - 2) cp_async_wait<1>();
        else cp_async_wait<0>();
        __syncthreads();
        if (ch + 3 < NSTEP_PROJ) load_chunk(ch + 3, (ch + 3) & 3);

        const uint32_t aB = aBase + (ch & 3) * TILE_BYTES;
        const uint32_t bB = bBase + (ch & 3) * TILE_BYTES;
#pragma unroll
        for (int kk = 0; kk < 2; kk++) {
            uint32_t afr[4][4];
#pragma unroll
            for (int mt = 0; mt < 4; mt++) {
                uint32_t addr = aB + (m_off + mt * 16 + lrow) * TPAD + kk * 32 + lseg;
                ldmatrix_x4(afr[mt][0], afr[mt][1], afr[mt][2], afr[mt][3], addr);
            }
            uint32_t bfr[4][2];
#pragma unroll
            for (int np = 0; np < 2; np++) {
                uint32_t q0, q1, q2, q3;
                uint32_t addr = bB + (n_off + np * 16 + lrow) * TPAD + kk * 32 + lseg;
                ldmatrix_x4(q0, q1, q2, q3, addr);
                bfr[np * 2][0] = q0; bfr[np * 2][1] = q2;
                bfr[np * 2 + 1][0] = q1; bfr[np * 2 + 1][1] = q3;
            }
#pragma unroll
            for (int mt = 0; mt < 4; mt++)
#pragma unroll
                for (int nt = 0; nt < 4; nt++)
                    mma_bf16(acc[mt][nt], afr[mt], bfr[nt]);
        }
    }
    __syncthreads();

    // epilogue: bias, write fp32 proj and fp16 copy
    const int gr = lane >> 2, tig = lane & 3;
#pragma unroll
    for (int mt = 0; mt < 4; mt++) {
        const int r0l = m_off + mt * 16 + gr;
        const int r1l = r0l + 8;
        const size_t gr0 = (size_t)(i0 + r0l), gr1 = (size_t)(i0 + r1l);
#pragma unroll
        for (int nt = 0; nt < 4; nt++) {
            const int cl = n_off + nt * 8 + tig * 2;
            float v00 = acc[mt][nt][0] + bsh[cl];
            float v01 = acc[mt][nt][1] + bsh[cl + 1];
            float v10 = acc[mt][nt][2] + bsh[cl];
            float v11 = acc[mt][nt][3] + bsh[cl + 1];
            *(float2*)(g_proj + gr0 * D + e0 + cl) = make_float2(v00, v01);
            *(float2*)(g_proj + gr1 * D + e0 + cl) = make_float2(v10, v11);
            *(__half2*)(g_qh + gr0 * 256 + e0 + cl) =
                __halves2half2(__float2half(v00), __float2half(v01));
            *(__half2*)(g_qh + gr1 * 256 + e0 + cl) =
                __halves2half2(__float2half(v10), __float2half(v11));
        }
    }
}

// ---------------- K2: per-row rnorm and sigmoid scalar -----------------------------
__global__ void k_rowstats(const float* __restrict__ ws, const float* __restrict__ bs) {
    int row = blockIdx.x * 8 + (threadIdx.x >> 5);
    int lane = threadIdx.x & 31;
    const float* p = g_proj + (size_t)row * D;
    float ss = 0.f, dt = 0.f;
#pragma unroll
    for (int j = 0; j < 8; j++) {
        float v = p[lane + j * 32];
        ss += v * v;
        dt += v * ws[lane + j * 32];
    }
#pragma unroll
    for (int o = 16; o > 0; o >>= 1) {
        ss += __shfl_xor_sync(0xffffffffu, ss, o);
        dt += __shfl_xor_sync(0xffffffffu, dt, o);
    }
    if (lane == 0) {
        g_rnorm[row] = 1.0f / fmaxf(sqrtf(ss), 1e-12f);
        g_s[row] = 1.0f / (1.0f + expf(-(dt + bs[0])));
    }
}

// ---------------- K3: adj GEMM via warp fp16 mma.sync (K=256), symmetric -----------
__global__ void __launch_bounds__(256, 2) k_adj_mma(float* __restrict__ adj_out) {
    extern __shared__ __align__(16) char dynsm[];
    char* smA = dynsm;
    char* smB = dynsm + NBUF * TILE_BYTES;
    float* aux = (float*)(dynsm + MMA_BUF_BYTES);
    float* rI = aux;          float* sI = aux + 128;
    float* rM = aux + 256;    float* sM = aux + 384;
    float* sdeg = aux + 512;  float* sdegM = aux + 640;

    const int tid = threadIdx.x;
    const int lane = tid & 31, w = tid >> 5;
    const int b = blockIdx.z;

    // map blockIdx.x (0..135) -> upper-triangle tile (ti, tj), ti<=tj, 16x16
    int ti = 0, rem = blockIdx.x;
    while (rem >= 16 - ti) { rem -= 16 - ti; ti++; }
    const int tj = ti + rem;
    const int i0 = ti * 128;
    const int m0 = tj * 128;
    const bool offdiag = (ti != tj);

    if (tid < 128) {
        rI[tid] = g_rnorm[b * N + i0 + tid];
        sI[tid] = g_s[b * N + i0 + tid];
        sdeg[tid] = 0.f;
    } else {
        int t = tid - 128;
        rM[t] = g_rnorm[b * N + m0 + t];
        sM[t] = g_s[b * N + m0 + t];
        sdegM[t] = 0.f;
    }

    const __half* QA = g_qh + (size_t)(b * N + i0) * 256;
    const __half* QB = g_qh + (size_t)(b * N + m0) * 256;
    const uint32_t aBase = smem_to_u32(smA);
    const uint32_t bBase = smem_to_u32(smB);

    const int r0c = (tid + 0)   >> 2, c0c = (tid + 0)   & 3;
    const int r1c = (tid + 256) >> 2, c1c = (tid + 256) & 3;

    auto load_chunk = [&](int s, int buf) {
        int kb = s * 32;
        uint32_t aB = aBase + buf * TILE_BYTES;
        uint32_t bB = bBase + buf * TILE_BYTES;
        cp_async16(aB + r0c * TPAD + c0c * 16, QA + (size_t)r0c * 256 + kb + c0c * 8);
        cp_async16(aB + r1c * TPAD + c1c * 16, QA + (size_t)r1c * 256 + kb + c1c * 8);
        cp_async16(bB + r0c * TPAD + c0c * 16, QB + (size_t)r0c * 256 + kb + c0c * 8);
        cp_async16(bB + r1c * TPAD + c1c * 16, QB + (size_t)r1c * 256 + kb + c1c * 8);
        cp_async_commit();
    };

    const int m_off = (w & 1) * 64;
    const int n_off = (w >> 1) * 32;
    const int lrow = lane & 15;
    const int lseg = (lane >> 4) * 16;

    float acc[4][4][4] = {};

    load_chunk(0, 0); load_chunk(1, 1); load_chunk(2, 2);
    for (int ch = 0; ch < NSTEP_ADJ; ch++) {
        if (ch <= NSTEP_ADJ - 3) cp_async_wait<2>();
        else if (ch == NSTEP_ADJ - 2) cp_async_wait<1>();
        else cp_async_wait<0>();
        __syncthreads();
        if (ch + 3 < NSTEP_ADJ) load_chunk(ch + 3, (ch + 3) & 3);

        const uint32_t aB = aBase + (ch & 3) * TILE_BYTES;
        const uint32_t bB = bBase + (ch & 3) * TILE_BYTES;
#pragma unroll
        for (int kk = 0; kk < 2; kk++) {
            uint32_t afr[4][4];
#pragma unroll
            for (int mt = 0; mt < 4; mt++) {
                uint32_t addr = aB + (m_off + mt * 16 + lrow) * TPAD + kk * 32 + lseg;
                ldmatrix_x4(afr[mt][0], afr[mt][1], afr[mt][2], afr[mt][3], addr);
            }
            uint32_t bfr[4][2];
#pragma unroll
            for (int np = 0; np < 2; np++) {
                uint32_t q0, q1, q2, q3;
                uint32_t addr = bB + (n_off + np * 16 + lrow) * TPAD + kk * 32 + lseg;
                ldmatrix_x4(q0, q1, q2, q3, addr);
                bfr[np * 2][0] = q0; bfr[np * 2][1] = q2;
                bfr[np * 2 + 1][0] = q1; bfr[np * 2 + 1][1] = q3;
            }
#pragma unroll
            for (int mt = 0; mt < 4; mt++)
#pragma unroll
                for (int nt = 0; nt < 4; nt++)
                    mma_f16(acc[mt][nt], afr[mt], bfr[nt]);
        }
    }
    __syncthreads();

    // ---- epilogue: scale, clamp, write normal block, row sums + column sums ----
    const int gr = lane >> 2, tig = lane & 3;
    float cs0[4] = {}, cs1[4] = {};
#pragma unroll
    for (int mt = 0; mt < 4; mt++) {
        const int r0l = m_off + mt * 16 + gr;
        const int r1l = r0l + 8;
        const float rn0 = rI[r0l], s0 = sI[r0l];
        const float rn1 = rI[r1l], s1 = sI[r1l];
        float* row0p = adj_out + ((size_t)(b * N + i0 + r0l)) * N + m0;
        float* row1p = adj_out + ((size_t)(b * N + i0 + r1l)) * N + m0;
        float d0 = 0.f, d1 = 0.f;
#pragma unroll
        for (int nt = 0; nt < 4; nt++) {
            const int cl = n_off + nt * 8 + tig * 2;
            const float rmA = rM[cl], rmB = rM[cl + 1];
            const float smA_ = sM[cl], smB_ = sM[cl + 1];
            float v00 = fmaxf(fminf(fmaxf(0.5f * (s0 + smA_), 1e-6f), 1.0f) *
                              (acc[mt][nt][0] * rn0 * rmA), 1e-6f);
            float v01 = fmaxf(fminf(fmaxf(0.5f * (s0 + smB_), 1e-6f), 1.0f) *
                              (acc[mt][nt][1] * rn0 * rmB), 1e-6f);
            float v10 = fmaxf(fminf(fmaxf(0.5f * (s1 + smA_), 1e-6f), 1.0f) *
                              (acc[mt][nt][2] * rn1 * rmA), 1e-6f);
            float v11 = fmaxf(fminf(fmaxf(0.5f * (s1 + smB_), 1e-6f), 1.0f) *
                              (acc[mt][nt][3] * rn1 * rmB), 1e-6f);
            d0 += v00 + v01;
            d1 += v10 + v11;
            cs0[nt] += v00 + v10;
            cs1[nt] += v01 + v11;
            *(float2*)(row0p + cl) = make_float2(v00, v01);
            *(float2*)(row1p + cl) = make_float2(v10, v11);
        }
        d0 += __shfl_xor_sync(0xffffffffu, d0, 1);
        d0 += __shfl_xor_sync(0xffffffffu, d0, 2);
        d1 += __shfl_xor_sync(0xffffffffu, d1, 1);
        d1 += __shfl_xor_sync(0xffffffffu, d1, 2);
        if (tig == 0) {
            atomicAdd(&sdeg[r0l], d0);
            atomicAdd(&sdeg[r1l], d1);
        }
    }
    if (offdiag) {
#pragma unroll
        for (int nt = 0; nt < 4; nt++) {
            float c0 = cs0[nt], c1 = cs1[nt];
#pragma unroll
            for (int o = 4; o < 32; o <<= 1) {
                c0 += __shfl_xor_sync(0xffffffffu, c0, o);
                c1 += __shfl_xor_sync(0xffffffffu, c1, o);
            }
            if (lane < 4) {
                atomicAdd(&sdegM[n_off + nt * 8 + tig * 2], c0);
                atomicAdd(&sdegM[n_off + nt * 8 + tig * 2 + 1], c1);
            }
        }
    }
    __syncthreads();
    if (tid < 128) atomicAdd(&g_deg[b * N + i0 + tid], sdeg[tid]);
    if (offdiag && tid >= 128)
        atomicAdd(&g_deg[b * N + m0 + (tid - 128)], sdegM[tid - 128]);

    // ---- mirror block via smem transpose stage (off-diagonal tiles only) ----
    if (offdiag) {
        float* stage = (float*)dynsm;      // reuse A buffers (16.9 KB needed)
        for (int cc = 0; cc < 4; cc++) {
            __syncthreads();
            if ((w >> 1) == cc) {
#pragma unroll
                for (int mt = 0; mt < 4; mt++) {
                    const int r0l = m_off + mt * 16 + gr;
                    const int r1l = r0l + 8;
                    const float rn0 = rI[r0l], s0 = sI[r0l];
                    const float rn1 = rI[r1l], s1 = sI[r1l];
#pragma unroll
                    for (int nt = 0; nt < 4; nt++) {
                        const int cl = n_off + nt * 8 + tig * 2;
                        const int cL = nt * 8 + tig * 2;
                        const float rmA = rM[cl], rmB = rM[cl + 1];
                        const float smA_ = sM[cl], smB_ = sM[cl + 1];
                        stage[cL * 132 + r0l] =
                            fmaxf(fminf(fmaxf(0.5f * (s0 + smA_), 1e-6f), 1.0f) *
                                  (acc[mt][nt][0] * rn0 * rmA), 1e-6f);
                        stage[(cL + 1) * 132 + r0l] =
                            fmaxf(fminf(fmaxf(0.5f * (s0 + smB_), 1e-6f), 1.0f) *
                                  (acc[mt][nt][1] * rn0 * rmB), 1e-6f);
                        stage[cL * 132 + r1l] =
                            fmaxf(fminf(fmaxf(0.5f * (s1 + smA_), 1e-6f), 1.0f) *
                                  (acc[mt][nt][2] * rn1 * rmA), 1e-6f);
                        stage[(cL + 1) * 132 + r1l] =
                            fmaxf(fminf(fmaxf(0.5f * (s1 + smB_), 1e-6f), 1.0f) *
                                  (acc[mt][nt][3] * rn1 * rmB), 1e-6f);
                    }
                }
            }
            __syncthreads();
            const int c = tid >> 3, seg = tid & 7;
            float* dst = adj_out + ((size_t)(b * N + m0 + cc * 32 + c)) * N + i0 + seg * 16;
            const float* srcp = stage + c * 132 + seg * 16;
#pragma unroll
            for (int j = 0; j < 4; j++)
                ((float4*)dst)[j] = make_float4(srcp[4*j], srcp[4*j+1], srcp[4*j+2], srcp[4*j+3]);
        }
    }
}

// ---------------- K-rdeg: reciprocal degrees --------------------------------------
__global__ void k_rdeg() {
    int t = blockIdx.x * blockDim.x + threadIdx.x;
    if (t < BN) g_rdeg[t] = 1.0f / fmaxf(g_deg[t], 1e-6f);
}

// ---------------- K4: w[m] = sum_i adj[m,i] * rdeg[i]  (adj symmetric) -------------
__global__ void k_wacc_row(const float* __restrict__ adj) {
    const int b = blockIdx.y;
    const int m = blockIdx.x * 8 + (threadIdx.x >> 5);
    const int lane = threadIdx.x & 31;
    const float4* A = (const float4*)(adj + ((size_t)(b * N + m)) * N);
    const float4* rd = (const float4*)(g_rdeg + b * N);
    float acc = 0.f;
#pragma unroll 4
    for (int j = 0; j < 16; j++) {
        int i = lane + j * 32;
        float4 a = A[i], r = rd[i];
        acc += a.x * r.x + a.y * r.y + a.z * r.z + a.w * r.w;
    }
#pragma unroll
    for (int o = 16; o > 0; o >>= 1) acc += __shfl_xor_sync(0xffffffffu, acc, o);
    if (lane == 0) g_w[b * N + m] = acc;
}

// ---------------- K5: xsum[b][d] = sum_n x[b][n][d] -------------------------------
__global__ void k_xsum(const float* __restrict__ x) {
    const int b = blockIdx.y, n0 = blockIdx.x * 64, d = threadIdx.x;
    const float* X = x + (size_t)(b * N + n0) * D;
    float acc = 0.f;
#pragma unroll 8
    for (int n = 0; n < 64; n++) acc += X[n * D + d];
    atomicAdd(&g_xsum[b * D + d], acc);
}

// ---------------- K6: rbar[b][d] = sum_m w[m]*proj[b][m][d] -----------------------
__global__ void k_rbar() {
    __shared__ float wS[64];
    const int b = blockIdx.y, m0 = blockIdx.x * 64, d = threadIdx.x;
    if (d < 64) wS[d] = g_w[b * N + m0 + d];
    __syncthreads();
    const float* P = g_proj + (size_t)(b * N + m0) * D;
    float acc = 0.f;
#pragma unroll 8
    for (int m = 0; m < 64; m++) acc += P[m * D + d] * wS[m];
    atomicAdd(&g_rbar[b * D + d], acc);
}

// ---------------- K7: final projections + LayerNorm -> out[b][d] ------------------
__global__ void k_final(const float* __restrict__ W_rp, const float* __restrict__ b_rp,
                        const float* __restrict__ W_gp, const float* __restrict__ b_gp,
                        const float* __restrict__ gamma, const float* __restrict__ beta,
                        float* __restrict__ out) {
    __shared__ float v[256];
    __shared__ float red[8];
    __shared__ float bcast;
    const int b = blockIdx.x, e = threadIdx.x;
    const int lane = e & 31, warp = e >> 5;

    v[e] = g_rbar[b * D + e] * (1.0f / (float)N);
    __syncthreads();

    float g1 = b_rp[e];
#pragma unroll 4
    for (int d = 0; d < D; d++) g1 += v[d] * W_rp[d * D + e];
    __syncthreads();
    v[e] = g1;
    __syncthreads();

    float g2 = b_gp[e];
#pragma unroll 4
    for (int d = 0; d < D; d++) g2 += v[d] * W_gp[d * D + e];

    float h = g2 + g_xsum[b * D + e] * (1.0f / (float)N);

    float sum = h;
#pragma unroll
    for (int o = 16; o > 0; o >>= 1) sum += __shfl_xor_sync(0xffffffffu, sum, o);
    if (lane == 0) red[warp] = sum;
    __syncthreads();
    if (e == 0) {
        float s = 0.f;
        for (int i = 0; i < 8; i++) s += red[i];
        bcast = s * (1.0f / (float)D);
    }
    __syncthreads();
    float mu = bcast;
    float c = h - mu;
    float sq = c * c;
#pragma unroll
    for (int o = 16; o > 0; o >>= 1) sq += __shfl_xor_sync(0xffffffffu, sq, o);
    __syncthreads();
    if (lane == 0) red[warp] = sq;
    __syncthreads();
    if (e == 0) {
        float s = 0.f;
        for (int i = 0; i < 8; i++) s += red[i];
        bcast = s * (1.0f / (float)D);
    }
    __syncthreads();
    float var = bcast;
    out[b * D + e] = c * rsqrtf(var + 1e-5f) * gamma[e] + beta[e];
}

// ---------------- launch ----------------------------------------------------------
extern "C" void kernel_launch(void* const* d_in, const int* in_sizes, int n_in,
                              void* d_out, int out_size) {
    const float* x    = (const float*)d_in[0];
    const float* W_fp = (const float*)d_in[1];
    const float* b_fp = (const float*)d_in[2];
    const float* w_s  = (const float*)d_in[3];
    const float* b_s  = (const float*)d_in[4];
    const float* W_rp = (const float*)d_in[5];
    const float* b_rp = (const float*)d_in[6];
    const float* W_gp = (const float*)d_in[7];
    const float* b_gp = (const float*)d_in[8];
    const float* gamma= (const float*)d_in[9];
    const float* beta = (const float*)d_in[10];

    float* out = (float*)d_out;        // [B,1,D] = 2048 floats
    float* adj = out + B * D;          // [B,N,N] follows

    cudaFuncSetAttribute(k_adj_mma, cudaFuncAttributeMaxDynamicSharedMemorySize, ADJ_SMEM);
    cudaFuncSetAttribute(k_proj_mma, cudaFuncAttributeMaxDynamicSharedMemorySize, PROJ_SMEM);

    k_zero<<<64, 256>>>();
    k_split<<<(BN * D + D * D) / 256, 256>>>(x, W_fp);
    k_proj_mma<<<dim3(BN / 128, 2), 256, PROJ_SMEM>>>(b_fp);
    k_rowstats<<<BN / 8, 256>>>(w_s, b_s);
    k_adj_mma<<<dim3(136, 1, B), 256, ADJ_SMEM>>>(adj);
    k_rdeg<<<64, 256>>>();
    k_xsum<<<dim3(N / 64, B), 256>>>(x);
    k_wacc_row<<<dim3(N / 8, B), 256>>>(adj);
    k_rbar<<<dim3(N / 64, B), 256>>>();
    k_final<<<B, 256>>>(W_rp, b_rp, W_gp, b_gp, gamma, beta, out);
}

// round 7
// speedup vs baseline: 3.6746x; 1.0838x over previous
#include <cuda_runtime.h>
#include <cuda_bf16.h>
#include <cuda_fp16.h>
#include <math.h>
#include <cstdint>

// Problem constants
#define B 8
#define N 2048
#define D 256
#define BN (B*N)           // 16384 rows

// ---------------- scratch (__device__ globals; no allocations allowed) ----------
__device__ float g_proj[BN * D];                  // 16 MB: proj = x@W_fp + b_fp
__device__ __half g_qh[(size_t)BN * 256];         // 8.4 MB: fp16 of proj (adj GEMM input)
__device__ __half g_xq[(size_t)BN * 256];         // 8.4 MB: fp16 of x
__device__ __half g_wq[256 * 256];                // fp16 of W_fp^T (row e, col d)
__device__ float g_rnorm[BN];        // 1/max(||proj_row||,1e-12)
__device__ float g_s[BN];            // sigmoid(proj·w_s + b_s)
__device__ float g_deg[BN];          // row sums of adj (atomic)
__device__ float g_w[BN];            // w[m] = sum_i adj[m,i]/deg[i]
__device__ float g_xsum[B * D];      // sum_n x[b,n,d] (atomic)
__device__ float g_rbar[B * D];      // sum_m w[m]*proj[b,m,d] (atomic)

// ======================= helpers (arch-agnostic PTX only) ==========================
__device__ __forceinline__ uint32_t smem_to_u32(const void* smem_ptr) {
    uint32_t addr;
    asm("{ .reg .u64 tmp; cvta.to.shared.u64 tmp, %1; cvt.u32.u64 %0, tmp; }"
        : "=r"(addr) : "l"(smem_ptr));
    return addr;
}
template<int NG>
__device__ __forceinline__ void cp_async_wait() {
    asm volatile("cp.async.wait_group %0;" :: "n"(NG));
}
__device__ __forceinline__ void cp_async16(uint32_t dst, const void* src) {
    asm volatile("cp.async.cg.shared.global [%0], [%1], 16;" :: "r"(dst), "l"(src));
}
__device__ __forceinline__ void cp_async_commit() {
    asm volatile("cp.async.commit_group;" ::: "memory");
}
__device__ __forceinline__ void ldmatrix_x4(uint32_t& r0, uint32_t& r1,
                                            uint32_t& r2, uint32_t& r3, uint32_t addr) {
    asm volatile("ldmatrix.sync.aligned.m8n8.x4.shared.b16 {%0,%1,%2,%3}, [%4];"
                 : "=r"(r0), "=r"(r1), "=r"(r2), "=r"(r3) : "r"(addr));
}
__device__ __forceinline__ void mma_f16(float* c, const uint32_t* a, const uint32_t* b) {
    asm volatile(
        "mma.sync.aligned.m16n8k16.row.col.f32.f16.f16.f32 "
        "{%0,%1,%2,%3}, {%4,%5,%6,%7}, {%8,%9}, {%0,%1,%2,%3};"
        : "+f"(c[0]), "+f"(c[1]), "+f"(c[2]), "+f"(c[3])
        : "r"(a[0]), "r"(a[1]), "r"(a[2]), "r"(a[3]), "r"(b[0]), "r"(b[1]));
}

#define TPAD 80
#define TILE_BYTES (128 * TPAD)     // 10240
#define NBUF 4
#define NSTEP 8
#define MMA_BUF_BYTES (NBUF * TILE_BYTES * 2)      // 81920
#define ADJ_SMEM (MMA_BUF_BYTES + 6 * 128 * 4)     // + rI,sI,rM,sM,sdeg,sdegM
#define PROJ_SMEM (MMA_BUF_BYTES + 512)            // + bias[128]

// ---------------- K-split: fp16 of x and W^T --------------------------------------
__global__ void k_split(const float* __restrict__ x, const float* __restrict__ W) {
    int idx = blockIdx.x * 256 + threadIdx.x;
    if (idx < BN * D) {
        g_xq[idx] = __float2half(x[idx]);
    } else {
        int j = idx - BN * D;          // j < D*D
        int e = j >> 8, d = j & 255;
        g_wq[e * 256 + d] = __float2half(W[d * D + e]);
    }
}

// ---------------- K1: proj GEMM on tensor cores (fp16, K=256) ----------------------
__global__ void __launch_bounds__(256, 2) k_proj_mma(const float* __restrict__ bias) {
    extern __shared__ __align__(16) char dynsm[];
    char* smA = dynsm;
    char* smB = dynsm + NBUF * TILE_BYTES;
    float* bsh = (float*)(dynsm + MMA_BUF_BYTES);

    const int tid = threadIdx.x;
    const int lane = tid & 31, w = tid >> 5;
    const int i0 = blockIdx.x * 128;
    const int e0 = blockIdx.y * 128;

    if (tid < 128) bsh[tid] = bias[e0 + tid];

    const __half* QA = g_xq + (size_t)i0 * 256;
    const __half* QB = g_wq + (size_t)e0 * 256;
    const uint32_t aBase = smem_to_u32(smA);
    const uint32_t bBase = smem_to_u32(smB);

    const int r0c = (tid + 0)   >> 2, c0c = (tid + 0)   & 3;
    const int r1c = (tid + 256) >> 2, c1c = (tid + 256) & 3;

    auto load_chunk = [&](int s, int buf) {
        int kb = s * 32;
        uint32_t aB = aBase + buf * TILE_BYTES;
        uint32_t bB = bBase + buf * TILE_BYTES;
        cp_async16(aB + r0c * TPAD + c0c * 16, QA + (size_t)r0c * 256 + kb + c0c * 8);
        cp_async16(aB + r1c * TPAD + c1c * 16, QA + (size_t)r1c * 256 + kb + c1c * 8);
        cp_async16(bB + r0c * TPAD + c0c * 16, QB + (size_t)r0c * 256 + kb + c0c * 8);
        cp_async16(bB + r1c * TPAD + c1c * 16, QB + (size_t)r1c * 256 + kb + c1c * 8);
        cp_async_commit();
    };

    const int m_off = (w & 1) * 64;
    const int n_off = (w >> 1) * 32;
    const int lrow = lane & 15;
    const int lseg = (lane >> 4) * 16;

    float acc[4][4][4] = {};

    load_chunk(0, 0); load_chunk(1, 1); load_chunk(2, 2);
    for (int ch = 0; ch < NSTEP; ch++) {
        if (ch <= NSTEP - 3) cp_async_wait<2>();
        else if (ch == NSTEP - 2) cp_async_wait<1>();
        else cp_async_wait<0>();
        __syncthreads();
        if (ch + 3 < NSTEP) load_chunk(ch + 3, (ch + 3) & 3);

        const uint32_t aB = aBase + (ch & 3) * TILE_BYTES;
        const uint32_t bB = bBase + (ch & 3) * TILE_BYTES;
#pragma unroll
        for (int kk = 0; kk < 2; kk++) {
            uint32_t afr[4][4];
#pragma unroll
            for (int mt = 0; mt < 4; mt++) {
                uint32_t addr = aB + (m_off + mt * 16 + lrow) * TPAD + kk * 32 + lseg;
                ldmatrix_x4(afr[mt][0], afr[mt][1], afr[mt][2], afr[mt][3], addr);
            }
            uint32_t bfr[4][2];
#pragma unroll
            for (int np = 0; np < 2; np++) {
                uint32_t q0, q1, q2, q3;
                uint32_t addr = bB + (n_off + np * 16 + lrow) * TPAD + kk * 32 + lseg;
                ldmatrix_x4(q0, q1, q2, q3, addr);
                bfr[np * 2][0] = q0; bfr[np * 2][1] = q2;
                bfr[np * 2 + 1][0] = q1; bfr[np * 2 + 1][1] = q3;
            }
#pragma unroll
            for (int mt = 0; mt < 4; mt++)
#pragma unroll
                for (int nt = 0; nt < 4; nt++)
                    mma_f16(acc[mt][nt], afr[mt], bfr[nt]);
        }
    }
    __syncthreads();

    // epilogue: bias, write fp32 proj and fp16 copy
    const int gr = lane >> 2, tig = lane & 3;
#pragma unroll
    for (int mt = 0; mt < 4; mt++) {
        const int r0l = m_off + mt * 16 + gr;
        const int r1l = r0l + 8;
        const size_t gr0 = (size_t)(i0 + r0l), gr1 = (size_t)(i0 + r1l);
#pragma unroll
        for (int nt = 0; nt < 4; nt++) {
            const int cl = n_off + nt * 8 + tig * 2;
            float v00 = acc[mt][nt][0] + bsh[cl];
            float v01 = acc[mt][nt][1] + bsh[cl + 1];
            float v10 = acc[mt][nt][2] + bsh[cl];
            float v11 = acc[mt][nt][3] + bsh[cl + 1];
            *(float2*)(g_proj + gr0 * D + e0 + cl) = make_float2(v00, v01);
            *(float2*)(g_proj + gr1 * D + e0 + cl) = make_float2(v10, v11);
            *(__half2*)(g_qh + gr0 * 256 + e0 + cl) =
                __halves2half2(__float2half(v00), __float2half(v01));
            *(__half2*)(g_qh + gr1 * 256 + e0 + cl) =
                __halves2half2(__float2half(v10), __float2half(v11));
        }
    }
}

// ---------------- K2: per-row rnorm/sigmoid; also zeroes accumulators --------------
__global__ void k_rowstats(const float* __restrict__ ws, const float* __restrict__ bs) {
    int row = blockIdx.x * 8 + (threadIdx.x >> 5);
    int lane = threadIdx.x & 31;
    if (threadIdx.x == 0) {        // 2048 blocks cover all B*D accumulators
        g_xsum[blockIdx.x] = 0.f;
        g_rbar[blockIdx.x] = 0.f;
    }
    const float* p = g_proj + (size_t)row * D;
    float ss = 0.f, dt = 0.f;
#pragma unroll
    for (int j = 0; j < 8; j++) {
        float v = p[lane + j * 32];
        ss += v * v;
        dt += v * ws[lane + j * 32];
    }
#pragma unroll
    for (int o = 16; o > 0; o >>= 1) {
        ss += __shfl_xor_sync(0xffffffffu, ss, o);
        dt += __shfl_xor_sync(0xffffffffu, dt, o);
    }
    if (lane == 0) {
        g_rnorm[row] = 1.0f / fmaxf(sqrtf(ss), 1e-12f);
        g_s[row] = 1.0f / (1.0f + expf(-(dt + bs[0])));
        g_deg[row] = 0.f;
    }
}

// ---------------- K3: adj GEMM via warp fp16 mma.sync (K=256), symmetric -----------
__global__ void __launch_bounds__(256, 2) k_adj_mma(float* __restrict__ adj_out) {
    extern __shared__ __align__(16) char dynsm[];
    char* smA = dynsm;
    char* smB = dynsm + NBUF * TILE_BYTES;
    float* aux = (float*)(dynsm + MMA_BUF_BYTES);
    float* rI = aux;          float* sI = aux + 128;
    float* rM = aux + 256;    float* sM = aux + 384;
    float* sdeg = aux + 512;  float* sdegM = aux + 640;

    const int tid = threadIdx.x;
    const int lane = tid & 31, w = tid >> 5;
    const int b = blockIdx.z;

    // map blockIdx.x (0..135) -> upper-triangle tile (ti, tj), ti<=tj, 16x16
    int ti = 0, rem = blockIdx.x;
    while (rem >= 16 - ti) { rem -= 16 - ti; ti++; }
    const int tj = ti + rem;
    const int i0 = ti * 128;
    const int m0 = tj * 128;
    const bool offdiag = (ti != tj);

    if (tid < 128) {
        rI[tid] = g_rnorm[b * N + i0 + tid];
        sI[tid] = g_s[b * N + i0 + tid];
        sdeg[tid] = 0.f;
    } else {
        int t = tid - 128;
        rM[t] = g_rnorm[b * N + m0 + t];
        sM[t] = g_s[b * N + m0 + t];
        sdegM[t] = 0.f;
    }

    const __half* QA = g_qh + (size_t)(b * N + i0) * 256;
    const __half* QB = g_qh + (size_t)(b * N + m0) * 256;
    const uint32_t aBase = smem_to_u32(smA);
    const uint32_t bBase = smem_to_u32(smB);

    const int r0c = (tid + 0)   >> 2, c0c = (tid + 0)   & 3;
    const int r1c = (tid + 256) >> 2, c1c = (tid + 256) & 3;

    auto load_chunk = [&](int s, int buf) {
        int kb = s * 32;
        uint32_t aB = aBase + buf * TILE_BYTES;
        uint32_t bB = bBase + buf * TILE_BYTES;
        cp_async16(aB + r0c * TPAD + c0c * 16, QA + (size_t)r0c * 256 + kb + c0c * 8);
        cp_async16(aB + r1c * TPAD + c1c * 16, QA + (size_t)r1c * 256 + kb + c1c * 8);
        cp_async16(bB + r0c * TPAD + c0c * 16, QB + (size_t)r0c * 256 + kb + c0c * 8);
        cp_async16(bB + r1c * TPAD + c1c * 16, QB + (size_t)r1c * 256 + kb + c1c * 8);
        cp_async_commit();
    };

    const int m_off = (w & 1) * 64;
    const int n_off = (w >> 1) * 32;
    const int lrow = lane & 15;
    const int lseg = (lane >> 4) * 16;

    float acc[4][4][4] = {};

    load_chunk(0, 0); load_chunk(1, 1); load_chunk(2, 2);
    for (int ch = 0; ch < NSTEP; ch++) {
        if (ch <= NSTEP - 3) cp_async_wait<2>();
        else if (ch == NSTEP - 2) cp_async_wait<1>();
        else cp_async_wait<0>();
        __syncthreads();
        if (ch + 3 < NSTEP) load_chunk(ch + 3, (ch + 3) & 3);

        const uint32_t aB = aBase + (ch & 3) * TILE_BYTES;
        const uint32_t bB = bBase + (ch & 3) * TILE_BYTES;
#pragma unroll
        for (int kk = 0; kk < 2; kk++) {
            uint32_t afr[4][4];
#pragma unroll
            for (int mt = 0; mt < 4; mt++) {
                uint32_t addr = aB + (m_off + mt * 16 + lrow) * TPAD + kk * 32 + lseg;
                ldmatrix_x4(afr[mt][0], afr[mt][1], afr[mt][2], afr[mt][3], addr);
            }
            uint32_t bfr[4][2];
#pragma unroll
            for (int np = 0; np < 2; np++) {
                uint32_t q0, q1, q2, q3;
                uint32_t addr = bB + (n_off + np * 16 + lrow) * TPAD + kk * 32 + lseg;
                ldmatrix_x4(q0, q1, q2, q3, addr);
                bfr[np * 2][0] = q0; bfr[np * 2][1] = q2;
                bfr[np * 2 + 1][0] = q1; bfr[np * 2 + 1][1] = q3;
            }
#pragma unroll
            for (int mt = 0; mt < 4; mt++)
#pragma unroll
                for (int nt = 0; nt < 4; nt++)
                    mma_f16(acc[mt][nt], afr[mt], bfr[nt]);
        }
    }
    __syncthreads();

    // ---- epilogue: scale, clamp, write normal block, row sums + column sums ----
    const int gr = lane >> 2, tig = lane & 3;
    float cs0[4] = {}, cs1[4] = {};
#pragma unroll
    for (int mt = 0; mt < 4; mt++) {
        const int r0l = m_off + mt * 16 + gr;
        const int r1l = r0l + 8;
        const float rn0 = rI[r0l], s0 = sI[r0l];
        const float rn1 = rI[r1l], s1 = sI[r1l];
        float* row0p = adj_out + ((size_t)(b * N + i0 + r0l)) * N + m0;
        float* row1p = adj_out + ((size_t)(b * N + i0 + r1l)) * N + m0;
        float d0 = 0.f, d1 = 0.f;
#pragma unroll
        for (int nt = 0; nt < 4; nt++) {
            const int cl = n_off + nt * 8 + tig * 2;
            const float rmA = rM[cl], rmB = rM[cl + 1];
            const float smA_ = sM[cl], smB_ = sM[cl + 1];
            float v00 = fmaxf(fminf(fmaxf(0.5f * (s0 + smA_), 1e-6f), 1.0f) *
                              (acc[mt][nt][0] * rn0 * rmA), 1e-6f);
            float v01 = fmaxf(fminf(fmaxf(0.5f * (s0 + smB_), 1e-6f), 1.0f) *
                              (acc[mt][nt][1] * rn0 * rmB), 1e-6f);
            float v10 = fmaxf(fminf(fmaxf(0.5f * (s1 + smA_), 1e-6f), 1.0f) *
                              (acc[mt][nt][2] * rn1 * rmA), 1e-6f);
            float v11 = fmaxf(fminf(fmaxf(0.5f * (s1 + smB_), 1e-6f), 1.0f) *
                              (acc[mt][nt][3] * rn1 * rmB), 1e-6f);
            d0 += v00 + v01;
            d1 += v10 + v11;
            cs0[nt] += v00 + v10;
            cs1[nt] += v01 + v11;
            *(float2*)(row0p + cl) = make_float2(v00, v01);
            *(float2*)(row1p + cl) = make_float2(v10, v11);
        }
        d0 += __shfl_xor_sync(0xffffffffu, d0, 1);
        d0 += __shfl_xor_sync(0xffffffffu, d0, 2);
        d1 += __shfl_xor_sync(0xffffffffu, d1, 1);
        d1 += __shfl_xor_sync(0xffffffffu, d1, 2);
        if (tig == 0) {
            atomicAdd(&sdeg[r0l], d0);
            atomicAdd(&sdeg[r1l], d1);
        }
    }
    if (offdiag) {
#pragma unroll
        for (int nt = 0; nt < 4; nt++) {
            float c0 = cs0[nt], c1 = cs1[nt];
#pragma unroll
            for (int o = 4; o < 32; o <<= 1) {
                c0 += __shfl_xor_sync(0xffffffffu, c0, o);
                c1 += __shfl_xor_sync(0xffffffffu, c1, o);
            }
            if (lane < 4) {
                atomicAdd(&sdegM[n_off + nt * 8 + tig * 2], c0);
                atomicAdd(&sdegM[n_off + nt * 8 + tig * 2 + 1], c1);
            }
        }
    }
    __syncthreads();
    if (tid < 128) atomicAdd(&g_deg[b * N + i0 + tid], sdeg[tid]);
    if (offdiag && tid >= 128)
        atomicAdd(&g_deg[b * N + m0 + (tid - 128)], sdegM[tid - 128]);

    // ---- mirror block via smem transpose stage (off-diagonal tiles only) ----
    if (offdiag) {
        float* stage = (float*)dynsm;      // reuse A buffers (16.9 KB needed)
        for (int cc = 0; cc < 4; cc++) {
            __syncthreads();
            if ((w >> 1) == cc) {
#pragma unroll
                for (int mt = 0; mt < 4; mt++) {
                    const int r0l = m_off + mt * 16 + gr;
                    const int r1l = r0l + 8;
                    const float rn0 = rI[r0l], s0 = sI[r0l];
                    const float rn1 = rI[r1l], s1 = sI[r1l];
#pragma unroll
                    for (int nt = 0; nt < 4; nt++) {
                        const int cl = n_off + nt * 8 + tig * 2;
                        const int cL = nt * 8 + tig * 2;
                        const float rmA = rM[cl], rmB = rM[cl + 1];
                        const float smA_ = sM[cl], smB_ = sM[cl + 1];
                        stage[cL * 132 + r0l] =
                            fmaxf(fminf(fmaxf(0.5f * (s0 + smA_), 1e-6f), 1.0f) *
                                  (acc[mt][nt][0] * rn0 * rmA), 1e-6f);
                        stage[(cL + 1) * 132 + r0l] =
                            fmaxf(fminf(fmaxf(0.5f * (s0 + smB_), 1e-6f), 1.0f) *
                                  (acc[mt][nt][1] * rn0 * rmB), 1e-6f);
                        stage[cL * 132 + r1l] =
                            fmaxf(fminf(fmaxf(0.5f * (s1 + smA_), 1e-6f), 1.0f) *
                                  (acc[mt][nt][2] * rn1 * rmA), 1e-6f);
                        stage[(cL + 1) * 132 + r1l] =
                            fmaxf(fminf(fmaxf(0.5f * (s1 + smB_), 1e-6f), 1.0f) *
                                  (acc[mt][nt][3] * rn1 * rmB), 1e-6f);
                    }
                }
            }
            __syncthreads();
            const int c = tid >> 3, seg = tid & 7;
            float* dst = adj_out + ((size_t)(b * N + m0 + cc * 32 + c)) * N + i0 + seg * 16;
            const float* srcp = stage + c * 132 + seg * 16;
#pragma unroll
            for (int j = 0; j < 4; j++)
                ((float4*)dst)[j] = make_float4(srcp[4*j], srcp[4*j+1], srcp[4*j+2], srcp[4*j+3]);
        }
    }
}

// ---------------- K4: w[m] = sum_i adj[m,i] / max(deg[i],1e-6)  (adj symmetric) ----
__global__ void k_wacc_row(const float* __restrict__ adj) {
    __shared__ float rdeg[N];
    const int b = blockIdx.y;
    const int m = blockIdx.x * 8 + (threadIdx.x >> 5);
    const int lane = threadIdx.x & 31;
    for (int j = threadIdx.x; j < N; j += 256)
        rdeg[j] = 1.0f / fmaxf(g_deg[b * N + j], 1e-6f);
    __syncthreads();
    const float4* A = (const float4*)(adj + ((size_t)(b * N + m)) * N);
    const float4* rd = (const float4*)rdeg;
    float acc = 0.f;
#pragma unroll 4
    for (int j = 0; j < 16; j++) {
        int i = lane + j * 32;
        float4 a = A[i], r = rd[i];
        acc += a.x * r.x + a.y * r.y + a.z * r.z + a.w * r.w;
    }
#pragma unroll
    for (int o = 16; o > 0; o >>= 1) acc += __shfl_xor_sync(0xffffffffu, acc, o);
    if (lane == 0) g_w[b * N + m] = acc;
}

// ---------------- K5: xsum[b][d] = sum_n x[b][n][d] -------------------------------
__global__ void k_xsum(const float* __restrict__ x) {
    const int b = blockIdx.y, n0 = blockIdx.x * 64, d = threadIdx.x;
    const float* X = x + (size_t)(b * N + n0) * D;
    float acc = 0.f;
#pragma unroll 8
    for (int n = 0; n < 64; n++) acc += X[n * D + d];
    atomicAdd(&g_xsum[b * D + d], acc);
}

// ---------------- K6: rbar[b][d] = sum_m w[m]*proj[b][m][d] -----------------------
__global__ void k_rbar() {
    __shared__ float wS[64];
    const int b = blockIdx.y, m0 = blockIdx.x * 64, d = threadIdx.x;
    if (d < 64) wS[d] = g_w[b * N + m0 + d];
    __syncthreads();
    const float* P = g_proj + (size_t)(b * N + m0) * D;
    float acc = 0.f;
#pragma unroll 8
    for (int m = 0; m < 64; m++) acc += P[m * D + d] * wS[m];
    atomicAdd(&g_rbar[b * D + d], acc);
}

// ---------------- K7: final projections + LayerNorm -> out[b][d] ------------------
__global__ void k_final(const float* __restrict__ W_rp, const float* __restrict__ b_rp,
                        const float* __restrict__ W_gp, const float* __restrict__ b_gp,
                        const float* __restrict__ gamma, const float* __restrict__ beta,
                        float* __restrict__ out) {
    __shared__ float v[256];
    __shared__ float red[8];
    __shared__ float bcast;
    const int b = blockIdx.x, e = threadIdx.x;
    const int lane = e & 31, warp = e >> 5;

    v[e] = g_rbar[b * D + e] * (1.0f / (float)N);
    __syncthreads();

    float g1 = b_rp[e];
#pragma unroll 4
    for (int d = 0; d < D; d++) g1 += v[d] * W_rp[d * D + e];
    __syncthreads();
    v[e] = g1;
    __syncthreads();

    float g2 = b_gp[e];
#pragma unroll 4
    for (int d = 0; d < D; d++) g2 += v[d] * W_gp[d * D + e];

    float h = g2 + g_xsum[b * D + e] * (1.0f / (float)N);

    float sum = h;
#pragma unroll
    for (int o = 16; o > 0; o >>= 1) sum += __shfl_xor_sync(0xffffffffu, sum, o);
    if (lane == 0) red[warp] = sum;
    __syncthreads();
    if (e == 0) {
        float s = 0.f;
        for (int i = 0; i < 8; i++) s += red[i];
        bcast = s * (1.0f / (float)D);
    }
    __syncthreads();
    float mu = bcast;
    float c = h - mu;
    float sq = c * c;
#pragma unroll
    for (int o = 16; o > 0; o >>= 1) sq += __shfl_xor_sync(0xffffffffu, sq, o);
    __syncthreads();
    if (lane == 0) red[warp] = sq;
    __syncthreads();
    if (e == 0) {
        float s = 0.f;
        for (int i = 0; i < 8; i++) s += red[i];
        bcast = s * (1.0f / (float)D);
    }
    __syncthreads();
    float var = bcast;
    out[b * D + e] = c * rsqrtf(var + 1e-5f) * gamma[e] + beta[e];
}

// ---------------- launch ----------------------------------------------------------
extern "C" void kernel_launch(void* const* d_in, const int* in_sizes, int n_in,
                              void* d_out, int out_size) {
    const float* x    = (const float*)d_in[0];
    const float* W_fp = (const float*)d_in[1];
    const float* b_fp = (const float*)d_in[2];
    const float* w_s  = (const float*)d_in[3];
    const float* b_s  = (const float*)d_in[4];
    const float* W_rp = (const float*)d_in[5];
    const float* b_rp = (const float*)d_in[6];
    const float* W_gp = (const float*)d_in[7];
    const float* b_gp = (const float*)d_in[8];
    const float* gamma= (const float*)d_in[9];
    const float* beta = (const float*)d_in[10];

    float* out = (float*)d_out;        // [B,1,D] = 2048 floats
    float* adj = out + B * D;          // [B,N,N] follows

    cudaFuncSetAttribute(k_adj_mma, cudaFuncAttributeMaxDynamicSharedMemorySize, ADJ_SMEM);
    cudaFuncSetAttribute(k_proj_mma, cudaFuncAttributeMaxDynamicSharedMemorySize, PROJ_SMEM);

    k_split<<<(BN * D + D * D) / 256, 256>>>(x, W_fp);
    k_proj_mma<<<dim3(BN / 128, 2), 256, PROJ_SMEM>>>(b_fp);
    k_rowstats<<<BN / 8, 256>>>(w_s, b_s);
    k_adj_mma<<<dim3(136, 1, B), 256, ADJ_SMEM>>>(adj);
    k_xsum<<<dim3(N / 64, B), 256>>>(x);
    k_wacc_row<<<dim3(N / 8, B), 256>>>(adj);
    k_rbar<<<dim3(N / 64, B), 256>>>();
    k_final<<<B, 256>>>(W_rp, b_rp, W_gp, b_gp, gamma, beta, out);
}

// round 8
// speedup vs baseline: 4.1088x; 1.1182x over previous
#include <cuda_runtime.h>
#include <cuda_bf16.h>
#include <cuda_fp16.h>
#include <math.h>
#include <cstdint>

// Problem constants
#define B 8
#define N 2048
#define D 256
#define BN (B*N)           // 16384 rows
#define BD (B*D)           // 2048

// ---------------- scratch (__device__ globals; no allocations allowed) ----------
__device__ float g_proj[BN * D];                  // 16 MB: proj = x@W_fp + b_fp
__device__ __half g_qh[(size_t)BN * 256];         // 8.4 MB: fp16 of proj (adj GEMM input)
__device__ __half g_xq[(size_t)BN * 256];         // 8.4 MB: fp16 of x
__device__ __half g_wq[256 * 256];                // fp16 of W_fp^T (row e, col d)
__device__ float g_rnorm[BN];        // 1/max(||proj_row||,1e-12)
__device__ float g_s[BN];            // sigmoid(proj·w_s + b_s)
__device__ float g_deg[BN];          // row sums of adj (atomic)
__device__ float g_w[BN];            // w[m] = sum_i adj[m,i]/deg[i]
__device__ float g_xpart[32 * BD];   // partial sums of x over n (32 chunks)
__device__ float g_rpart[32 * BD];   // partial sums of w*proj over m (32 chunks)

// ======================= helpers (arch-agnostic PTX only) ==========================
__device__ __forceinline__ uint32_t smem_to_u32(const void* smem_ptr) {
    uint32_t addr;
    asm("{ .reg .u64 tmp; cvta.to.shared.u64 tmp, %1; cvt.u32.u64 %0, tmp; }"
        : "=r"(addr) : "l"(smem_ptr));
    return addr;
}
template<int NG>
__device__ __forceinline__ void cp_async_wait() {
    asm volatile("cp.async.wait_group %0;" :: "n"(NG));
}
__device__ __forceinline__ void cp_async16(uint32_t dst, const void* src) {
    asm volatile("cp.async.cg.shared.global [%0], [%1], 16;" :: "r"(dst), "l"(src));
}
__device__ __forceinline__ void cp_async_commit() {
    asm volatile("cp.async.commit_group;" ::: "memory");
}
__device__ __forceinline__ void ldmatrix_x4(uint32_t& r0, uint32_t& r1,
                                            uint32_t& r2, uint32_t& r3, uint32_t addr) {
    asm volatile("ldmatrix.sync.aligned.m8n8.x4.shared.b16 {%0,%1,%2,%3}, [%4];"
                 : "=r"(r0), "=r"(r1), "=r"(r2), "=r"(r3) : "r"(addr));
}
__device__ __forceinline__ void mma_f16(float* c, const uint32_t* a, const uint32_t* b) {
    asm volatile(
        "mma.sync.aligned.m16n8k16.row.col.f32.f16.f16.f32 "
        "{%0,%1,%2,%3}, {%4,%5,%6,%7}, {%8,%9}, {%0,%1,%2,%3};"
        : "+f"(c[0]), "+f"(c[1]), "+f"(c[2]), "+f"(c[3])
        : "r"(a[0]), "r"(a[1]), "r"(a[2]), "r"(a[3]), "r"(b[0]), "r"(b[1]));
}

#define TPAD 80
#define TILE_BYTES (128 * TPAD)     // 10240
#define NBUF 4
#define NSTEP 8
#define MMA_BUF_BYTES (NBUF * TILE_BYTES * 2)      // 81920 (stage 128x132 fp32 fits)
#define ADJ_SMEM (MMA_BUF_BYTES + 6 * 128 * 4)     // + rI,sI,rM,sM,sdeg,sdegM
#define PROJ_SMEM (MMA_BUF_BYTES + 512)            // + bias[128]

// ---------------- K-splitx: fp16 of x + partial xsum; fp16 of W^T -----------------
__global__ void k_splitx(const float* __restrict__ x, const float* __restrict__ W) {
    const int blk = blockIdx.x;
    const int d = threadIdx.x;
    if (blk < 256) {
        const int b = blk >> 5;            // 32 chunks per batch
        const int n0 = (blk & 31) * 64;
        const float* X = x + (size_t)(b * N + n0) * D;
        __half* Q = g_xq + (size_t)(b * N + n0) * 256;
        float acc = 0.f;
#pragma unroll 8
        for (int n = 0; n < 64; n++) {
            float v = X[n * D + d];
            acc += v;
            Q[n * 256 + d] = __float2half(v);
        }
        g_xpart[(blk & 31) * BD + b * D + d] = acc;
    } else {
        const int base = (blk - 256) * 16384;
        for (int i = 0; i < 64; i++) {
            int j = base + i * 256 + d;
            int e = j >> 8, dd = j & 255;
            g_wq[e * 256 + dd] = __float2half(W[dd * D + e]);
        }
    }
}

// ---------------- K1: proj GEMM on tensor cores (fp16, K=256) ----------------------
__global__ void __launch_bounds__(256, 2) k_proj_mma(const float* __restrict__ bias) {
    extern __shared__ __align__(16) char dynsm[];
    char* smA = dynsm;
    char* smB = dynsm + NBUF * TILE_BYTES;
    float* bsh = (float*)(dynsm + MMA_BUF_BYTES);

    const int tid = threadIdx.x;
    const int lane = tid & 31, w = tid >> 5;
    const int i0 = blockIdx.x * 128;
    const int e0 = blockIdx.y * 128;

    if (tid < 128) bsh[tid] = bias[e0 + tid];

    const __half* QA = g_xq + (size_t)i0 * 256;
    const __half* QB = g_wq + (size_t)e0 * 256;
    const uint32_t aBase = smem_to_u32(smA);
    const uint32_t bBase = smem_to_u32(smB);

    const int r0c = (tid + 0)   >> 2, c0c = (tid + 0)   & 3;
    const int r1c = (tid + 256) >> 2, c1c = (tid + 256) & 3;

    auto load_chunk = [&](int s, int buf) {
        int kb = s * 32;
        uint32_t aB = aBase + buf * TILE_BYTES;
        uint32_t bB = bBase + buf * TILE_BYTES;
        cp_async16(aB + r0c * TPAD + c0c * 16, QA + (size_t)r0c * 256 + kb + c0c * 8);
        cp_async16(aB + r1c * TPAD + c1c * 16, QA + (size_t)r1c * 256 + kb + c1c * 8);
        cp_async16(bB + r0c * TPAD + c0c * 16, QB + (size_t)r0c * 256 + kb + c0c * 8);
        cp_async16(bB + r1c * TPAD + c1c * 16, QB + (size_t)r1c * 256 + kb + c1c * 8);
        cp_async_commit();
    };

    const int m_off = (w & 1) * 64;
    const int n_off = (w >> 1) * 32;
    const int lrow = lane & 15;
    const int lseg = (lane >> 4) * 16;

    float acc[4][4][4] = {};

    load_chunk(0, 0); load_chunk(1, 1); load_chunk(2, 2);
    for (int ch = 0; ch < NSTEP; ch++) {
        if (ch <= NSTEP - 3) cp_async_wait<2>();
        else if (ch == NSTEP - 2) cp_async_wait<1>();
        else cp_async_wait<0>();
        __syncthreads();
        if (ch + 3 < NSTEP) load_chunk(ch + 3, (ch + 3) & 3);

        const uint32_t aB = aBase + (ch & 3) * TILE_BYTES;
        const uint32_t bB = bBase + (ch & 3) * TILE_BYTES;
#pragma unroll
        for (int kk = 0; kk < 2; kk++) {
            uint32_t afr[4][4];
#pragma unroll
            for (int mt = 0; mt < 4; mt++) {
                uint32_t addr = aB + (m_off + mt * 16 + lrow) * TPAD + kk * 32 + lseg;
                ldmatrix_x4(afr[mt][0], afr[mt][1], afr[mt][2], afr[mt][3], addr);
            }
            uint32_t bfr[4][2];
#pragma unroll
            for (int np = 0; np < 2; np++) {
                uint32_t q0, q1, q2, q3;
                uint32_t addr = bB + (n_off + np * 16 + lrow) * TPAD + kk * 32 + lseg;
                ldmatrix_x4(q0, q1, q2, q3, addr);
                bfr[np * 2][0] = q0; bfr[np * 2][1] = q2;
                bfr[np * 2 + 1][0] = q1; bfr[np * 2 + 1][1] = q3;
            }
#pragma unroll
            for (int mt = 0; mt < 4; mt++)
#pragma unroll
                for (int nt = 0; nt < 4; nt++)
                    mma_f16(acc[mt][nt], afr[mt], bfr[nt]);
        }
    }
    __syncthreads();

    // epilogue: bias, write fp32 proj and fp16 copy
    const int gr = lane >> 2, tig = lane & 3;
#pragma unroll
    for (int mt = 0; mt < 4; mt++) {
        const int r0l = m_off + mt * 16 + gr;
        const int r1l = r0l + 8;
        const size_t gr0 = (size_t)(i0 + r0l), gr1 = (size_t)(i0 + r1l);
#pragma unroll
        for (int nt = 0; nt < 4; nt++) {
            const int cl = n_off + nt * 8 + tig * 2;
            float v00 = acc[mt][nt][0] + bsh[cl];
            float v01 = acc[mt][nt][1] + bsh[cl + 1];
            float v10 = acc[mt][nt][2] + bsh[cl];
            float v11 = acc[mt][nt][3] + bsh[cl + 1];
            *(float2*)(g_proj + gr0 * D + e0 + cl) = make_float2(v00, v01);
            *(float2*)(g_proj + gr1 * D + e0 + cl) = make_float2(v10, v11);
            *(__half2*)(g_qh + gr0 * 256 + e0 + cl) =
                __halves2half2(__float2half(v00), __float2half(v01));
            *(__half2*)(g_qh + gr1 * 256 + e0 + cl) =
                __halves2half2(__float2half(v10), __float2half(v11));
        }
    }
}

// ---------------- K2: per-row rnorm/sigmoid from fp16 proj; zero g_deg -------------
__global__ void k_rowstats(const float* __restrict__ ws, const float* __restrict__ bs) {
    int row = blockIdx.x * 8 + (threadIdx.x >> 5);
    int lane = threadIdx.x & 31;
    const __half2* p = (const __half2*)(g_qh + (size_t)row * 256);
    const float2* w2 = (const float2*)ws;
    float ss = 0.f, dt = 0.f;
#pragma unroll
    for (int j = 0; j < 4; j++) {
        float2 v = __half22float2(p[lane + j * 32]);
        float2 wv = w2[lane + j * 32];
        ss += v.x * v.x + v.y * v.y;
        dt += v.x * wv.x + v.y * wv.y;
    }
#pragma unroll
    for (int o = 16; o > 0; o >>= 1) {
        ss += __shfl_xor_sync(0xffffffffu, ss, o);
        dt += __shfl_xor_sync(0xffffffffu, dt, o);
    }
    if (lane == 0) {
        g_rnorm[row] = 1.0f / fmaxf(sqrtf(ss), 1e-12f);
        g_s[row] = 1.0f / (1.0f + expf(-(dt + bs[0])));
        g_deg[row] = 0.f;
    }
}

// ---------------- K3: adj GEMM via warp fp16 mma.sync (K=256), symmetric -----------
__global__ void __launch_bounds__(256, 2) k_adj_mma(float* __restrict__ adj_out) {
    extern __shared__ __align__(16) char dynsm[];
    char* smA = dynsm;
    char* smB = dynsm + NBUF * TILE_BYTES;
    float* aux = (float*)(dynsm + MMA_BUF_BYTES);
    float* rI = aux;          float* sI = aux + 128;
    float* rM = aux + 256;    float* sM = aux + 384;
    float* sdeg = aux + 512;  float* sdegM = aux + 640;
    float* stage = (float*)dynsm;      // 128 x 132 fp32 = 67584 B, aliases MMA bufs

    const int tid = threadIdx.x;
    const int lane = tid & 31, w = tid >> 5;
    const int b = blockIdx.z;

    // map blockIdx.x (0..135) -> upper-triangle tile (ti, tj), ti<=tj, 16x16
    int ti = 0, rem = blockIdx.x;
    while (rem >= 16 - ti) { rem -= 16 - ti; ti++; }
    const int tj = ti + rem;
    const int i0 = ti * 128;
    const int m0 = tj * 128;
    const bool offdiag = (ti != tj);

    if (tid < 128) {
        rI[tid] = g_rnorm[b * N + i0 + tid];
        sI[tid] = g_s[b * N + i0 + tid];
        sdeg[tid] = 0.f;
    } else {
        int t = tid - 128;
        rM[t] = g_rnorm[b * N + m0 + t];
        sM[t] = g_s[b * N + m0 + t];
        sdegM[t] = 0.f;
    }

    const __half* QA = g_qh + (size_t)(b * N + i0) * 256;
    const __half* QB = g_qh + (size_t)(b * N + m0) * 256;
    const uint32_t aBase = smem_to_u32(smA);
    const uint32_t bBase = smem_to_u32(smB);

    const int r0c = (tid + 0)   >> 2, c0c = (tid + 0)   & 3;
    const int r1c = (tid + 256) >> 2, c1c = (tid + 256) & 3;

    auto load_chunk = [&](int s, int buf) {
        int kb = s * 32;
        uint32_t aB = aBase + buf * TILE_BYTES;
        uint32_t bB = bBase + buf * TILE_BYTES;
        cp_async16(aB + r0c * TPAD + c0c * 16, QA + (size_t)r0c * 256 + kb + c0c * 8);
        cp_async16(aB + r1c * TPAD + c1c * 16, QA + (size_t)r1c * 256 + kb + c1c * 8);
        cp_async16(bB + r0c * TPAD + c0c * 16, QB + (size_t)r0c * 256 + kb + c0c * 8);
        cp_async16(bB + r1c * TPAD + c1c * 16, QB + (size_t)r1c * 256 + kb + c1c * 8);
        cp_async_commit();
    };

    const int m_off = (w & 1) * 64;
    const int n_off = (w >> 1) * 32;
    const int lrow = lane & 15;
    const int lseg = (lane >> 4) * 16;

    float acc[4][4][4] = {};

    load_chunk(0, 0); load_chunk(1, 1); load_chunk(2, 2);
    for (int ch = 0; ch < NSTEP; ch++) {
        if (ch <= NSTEP - 3) cp_async_wait<2>();
        else if (ch == NSTEP - 2) cp_async_wait<1>();
        else cp_async_wait<0>();
        __syncthreads();
        if (ch + 3 < NSTEP) load_chunk(ch + 3, (ch + 3) & 3);

        const uint32_t aB = aBase + (ch & 3) * TILE_BYTES;
        const uint32_t bB = bBase + (ch & 3) * TILE_BYTES;
#pragma unroll
        for (int kk = 0; kk < 2; kk++) {
            uint32_t afr[4][4];
#pragma unroll
            for (int mt = 0; mt < 4; mt++) {
                uint32_t addr = aB + (m_off + mt * 16 + lrow) * TPAD + kk * 32 + lseg;
                ldmatrix_x4(afr[mt][0], afr[mt][1], afr[mt][2], afr[mt][3], addr);
            }
            uint32_t bfr[4][2];
#pragma unroll
            for (int np = 0; np < 2; np++) {
                uint32_t q0, q1, q2, q3;
                uint32_t addr = bB + (n_off + np * 16 + lrow) * TPAD + kk * 32 + lseg;
                ldmatrix_x4(q0, q1, q2, q3, addr);
                bfr[np * 2][0] = q0; bfr[np * 2][1] = q2;
                bfr[np * 2 + 1][0] = q1; bfr[np * 2 + 1][1] = q3;
            }
#pragma unroll
            for (int mt = 0; mt < 4; mt++)
#pragma unroll
                for (int nt = 0; nt < 4; nt++)
                    mma_f16(acc[mt][nt], afr[mt], bfr[nt]);
        }
    }
    __syncthreads();   // MMA buffers dead; stage writes may begin

    // ---- epilogue: scale, clamp, write normal block, stage mirror, row/col sums --
    const int gr = lane >> 2, tig = lane & 3;
    float cs0[4] = {}, cs1[4] = {};
#pragma unroll
    for (int mt = 0; mt < 4; mt++) {
        const int r0l = m_off + mt * 16 + gr;
        const int r1l = r0l + 8;
        const float rn0 = rI[r0l], s0 = sI[r0l];
        const float rn1 = rI[r1l], s1 = sI[r1l];
        float* row0p = adj_out + ((size_t)(b * N + i0 + r0l)) * N + m0;
        float* row1p = adj_out + ((size_t)(b * N + i0 + r1l)) * N + m0;
        float d0 = 0.f, d1 = 0.f;
#pragma unroll
        for (int nt = 0; nt < 4; nt++) {
            const int cl = n_off + nt * 8 + tig * 2;
            const float rmA = rM[cl], rmB = rM[cl + 1];
            const float smA_ = sM[cl], smB_ = sM[cl + 1];
            float v00 = fmaxf(fminf(fmaxf(0.5f * (s0 + smA_), 1e-6f), 1.0f) *
                              (acc[mt][nt][0] * rn0 * rmA), 1e-6f);
            float v01 = fmaxf(fminf(fmaxf(0.5f * (s0 + smB_), 1e-6f), 1.0f) *
                              (acc[mt][nt][1] * rn0 * rmB), 1e-6f);
            float v10 = fmaxf(fminf(fmaxf(0.5f * (s1 + smA_), 1e-6f), 1.0f) *
                              (acc[mt][nt][2] * rn1 * rmA), 1e-6f);
            float v11 = fmaxf(fminf(fmaxf(0.5f * (s1 + smB_), 1e-6f), 1.0f) *
                              (acc[mt][nt][3] * rn1 * rmB), 1e-6f);
            d0 += v00 + v01;
            d1 += v10 + v11;
            cs0[nt] += v00 + v10;
            cs1[nt] += v01 + v11;
            *(float2*)(row0p + cl) = make_float2(v00, v01);
            *(float2*)(row1p + cl) = make_float2(v10, v11);
            if (offdiag) {
                stage[cl * 132 + r0l] = v00;
                stage[(cl + 1) * 132 + r0l] = v01;
                stage[cl * 132 + r1l] = v10;
                stage[(cl + 1) * 132 + r1l] = v11;
            }
        }
        d0 += __shfl_xor_sync(0xffffffffu, d0, 1);
        d0 += __shfl_xor_sync(0xffffffffu, d0, 2);
        d1 += __shfl_xor_sync(0xffffffffu, d1, 1);
        d1 += __shfl_xor_sync(0xffffffffu, d1, 2);
        if (tig == 0) {
            atomicAdd(&sdeg[r0l], d0);
            atomicAdd(&sdeg[r1l], d1);
        }
    }
    if (offdiag) {
#pragma unroll
        for (int nt = 0; nt < 4; nt++) {
            float c0 = cs0[nt], c1 = cs1[nt];
#pragma unroll
            for (int o = 4; o < 32; o <<= 1) {
                c0 += __shfl_xor_sync(0xffffffffu, c0, o);
                c1 += __shfl_xor_sync(0xffffffffu, c1, o);
            }
            if (lane < 4) {
                atomicAdd(&sdegM[n_off + nt * 8 + tig * 2], c0);
                atomicAdd(&sdegM[n_off + nt * 8 + tig * 2 + 1], c1);
            }
        }
    }
    __syncthreads();   // sdeg/sdegM and stage complete
    if (tid < 128) atomicAdd(&g_deg[b * N + i0 + tid], sdeg[tid]);
    if (offdiag && tid >= 128)
        atomicAdd(&g_deg[b * N + m0 + (tid - 128)], sdegM[tid - 128]);

    // ---- mirror drain: warp per row, 512B coalesced stores ----
    if (offdiag) {
#pragma unroll
        for (int rr = 0; rr < 16; rr++) {
            int row = rr * 8 + w;
            const float4* src = (const float4*)(stage + row * 132);
            float4* dst = (float4*)(adj_out + ((size_t)(b * N + m0 + row)) * N + i0);
            dst[lane] = src[lane];
        }
    }
}

// ---------------- K4: w[m] = sum_i adj[m,i] / max(deg[i],1e-6)  (adj symmetric) ----
__global__ void k_wacc_row(const float* __restrict__ adj) {
    __shared__ float rdeg[N];
    const int b = blockIdx.y;
    const int m = blockIdx.x * 8 + (threadIdx.x >> 5);
    const int lane = threadIdx.x & 31;
    for (int j = threadIdx.x; j < N; j += 256)
        rdeg[j] = 1.0f / fmaxf(g_deg[b * N + j], 1e-6f);
    __syncthreads();
    const float4* A = (const float4*)(adj + ((size_t)(b * N + m)) * N);
    const float4* rd = (const float4*)rdeg;
    float acc = 0.f;
#pragma unroll 4
    for (int j = 0; j < 16; j++) {
        int i = lane + j * 32;
        float4 a = A[i], r = rd[i];
        acc += a.x * r.x + a.y * r.y + a.z * r.z + a.w * r.w;
    }
#pragma unroll
    for (int o = 16; o > 0; o >>= 1) acc += __shfl_xor_sync(0xffffffffu, acc, o);
    if (lane == 0) g_w[b * N + m] = acc;
}

// ---------------- K6: rpart[c][b][d] = sum_{m in chunk} w[m]*proj[b][m][d] --------
__global__ void k_rbar() {
    __shared__ float wS[64];
    const int b = blockIdx.y, m0 = blockIdx.x * 64, d = threadIdx.x;
    if (d < 64) wS[d] = g_w[b * N + m0 + d];
    __syncthreads();
    const float* P = g_proj + (size_t)(b * N + m0) * D;
    float acc = 0.f;
#pragma unroll 8
    for (int m = 0; m < 64; m++) acc += P[m * D + d] * wS[m];
    g_rpart[blockIdx.x * BD + b * D + d] = acc;
}

// ---------------- K7: final projections + LayerNorm -> out[b][d] ------------------
__global__ void k_final(const float* __restrict__ W_rp, const float* __restrict__ b_rp,
                        const float* __restrict__ W_gp, const float* __restrict__ b_gp,
                        const float* __restrict__ gamma, const float* __restrict__ beta,
                        float* __restrict__ out) {
    __shared__ float v[256];
    __shared__ float red[8];
    __shared__ float bcast;
    const int b = blockIdx.x, e = threadIdx.x;
    const int lane = e & 31, warp = e >> 5;

    float xs = 0.f, rb = 0.f;
#pragma unroll
    for (int c = 0; c < 32; c++) {
        xs += g_xpart[c * BD + b * D + e];
        rb += g_rpart[c * BD + b * D + e];
    }

    v[e] = rb * (1.0f / (float)N);
    __syncthreads();

    float g1 = b_rp[e];
#pragma unroll 4
    for (int d = 0; d < D; d++) g1 += v[d] * W_rp[d * D + e];
    __syncthreads();
    v[e] = g1;
    __syncthreads();

    float g2 = b_gp[e];
#pragma unroll 4
    for (int d = 0; d < D; d++) g2 += v[d] * W_gp[d * D + e];

    float h = g2 + xs * (1.0f / (float)N);

    float sum = h;
#pragma unroll
    for (int o = 16; o > 0; o >>= 1) sum += __shfl_xor_sync(0xffffffffu, sum, o);
    if (lane == 0) red[warp] = sum;
    __syncthreads();
    if (e == 0) {
        float s = 0.f;
        for (int i = 0; i < 8; i++) s += red[i];
        bcast = s * (1.0f / (float)D);
    }
    __syncthreads();
    float mu = bcast;
    float c = h - mu;
    float sq = c * c;
#pragma unroll
    for (int o = 16; o > 0; o >>= 1) sq += __shfl_xor_sync(0xffffffffu, sq, o);
    __syncthreads();
    if (lane == 0) red[warp] = sq;
    __syncthreads();
    if (e == 0) {
        float s = 0.f;
        for (int i = 0; i < 8; i++) s += red[i];
        bcast = s * (1.0f / (float)D);
    }
    __syncthreads();
    float var = bcast;
    out[b * D + e] = c * rsqrtf(var + 1e-5f) * gamma[e] + beta[e];
}

// ---------------- launch ----------------------------------------------------------
extern "C" void kernel_launch(void* const* d_in, const int* in_sizes, int n_in,
                              void* d_out, int out_size) {
    const float* x    = (const float*)d_in[0];
    const float* W_fp = (const float*)d_in[1];
    const float* b_fp = (const float*)d_in[2];
    const float* w_s  = (const float*)d_in[3];
    const float* b_s  = (const float*)d_in[4];
    const float* W_rp = (const float*)d_in[5];
    const float* b_rp = (const float*)d_in[6];
    const float* W_gp = (const float*)d_in[7];
    const float* b_gp = (const float*)d_in[8];
    const float* gamma= (const float*)d_in[9];
    const float* beta = (const float*)d_in[10];

    float* out = (float*)d_out;        // [B,1,D] = 2048 floats
    float* adj = out + B * D;          // [B,N,N] follows

    cudaFuncSetAttribute(k_adj_mma, cudaFuncAttributeMaxDynamicSharedMemorySize, ADJ_SMEM);
    cudaFuncSetAttribute(k_proj_mma, cudaFuncAttributeMaxDynamicSharedMemorySize, PROJ_SMEM);

    k_splitx<<<260, 256>>>(x, W_fp);
    k_proj_mma<<<dim3(BN / 128, 2), 256, PROJ_SMEM>>>(b_fp);
    k_rowstats<<<BN / 8, 256>>>(w_s, b_s);
    k_adj_mma<<<dim3(136, 1, B), 256, ADJ_SMEM>>>(adj);
    k_wacc_row<<<dim3(N / 8, B), 256>>>(adj);
    k_rbar<<<dim3(N / 64, B), 256>>>();
    k_final<<<B, 256>>>(W_rp, b_rp, W_gp, b_gp, gamma, beta, out);
}